// round 2
// baseline (speedup 1.0000x reference)
#include <cuda_runtime.h>

// Problem constants
#define SEQ   2048
#define BATCH 2
#define HID   1024
#define NROWS 4096          // BATCH*SEQ
#define PCOLS 4096          // 8 projections * 512 cols each
// P column layout: [Q(0) K(512) V(1024) LQ(1536) LK1(2048) LK2(2560) LV1(3072) LV2(3584)]

// Scratch (device globals: allocation-free per harness rules)
__device__ float g_P[(size_t)NROWS * PCOLS];          // 64 MB projections
__device__ float g_Mpart[8 * 16 * 64 * 64];           // split-K partials for M
__device__ float g_M[16 * 64 * 64];                   // per (b, local head) lk1^T lk1

struct ProjArgs {
    const float* w[8];
    const float* b[8];
};

// ---------------------------------------------------------------------------
// Kernel 1: fused projection GEMM.  g_P = X[4096,1024] @ Wcat[1024,4096] + bias
// 128x128 block tile, BK=8, 256 threads, 8x8 microtile per thread.
// ---------------------------------------------------------------------------
__global__ __launch_bounds__(256) void proj_gemm(const float* __restrict__ X, ProjArgs pa) {
    __shared__ float As[8 * 128];
    __shared__ float Bs[8 * 128];

    const int bm = blockIdx.y;
    const int bn = blockIdx.x;
    const int widx  = bn >> 2;                 // which of the 8 weight mats
    const int ncol0 = (bn & 3) * 128;          // local col within that W (fan_out=512)
    const float* __restrict__ W    = pa.w[widx];
    const float* __restrict__ bias = pa.b[widx];

    const int tid = threadIdx.x;
    const int tx = tid & 15;                   // col group
    const int ty = tid >> 4;                   // row group

    // load indices
    const int arow = tid >> 1;                 // 0..127
    const int acol = (tid & 1) * 4;            // 0 or 4
    const int brow = tid >> 5;                 // 0..7
    const int bcol = (tid & 31) * 4;           // 0..124

    float acc[8][8];
#pragma unroll
    for (int i = 0; i < 8; i++)
#pragma unroll
        for (int j = 0; j < 8; j++) acc[i][j] = 0.f;

    const float* Aptr = X + (size_t)(bm * 128 + arow) * HID + acol;
    const float* Bptr = W + (size_t)brow * 512 + ncol0 + bcol;

    for (int k0 = 0; k0 < HID; k0 += 8) {
        float4 av = *(const float4*)(Aptr + k0);
        float4 bv = *(const float4*)(Bptr + (size_t)k0 * 512);
        __syncthreads();
        As[(acol + 0) * 128 + arow] = av.x;
        As[(acol + 1) * 128 + arow] = av.y;
        As[(acol + 2) * 128 + arow] = av.z;
        As[(acol + 3) * 128 + arow] = av.w;
        *(float4*)&Bs[brow * 128 + bcol] = bv;
        __syncthreads();
#pragma unroll
        for (int k = 0; k < 8; k++) {
            float ar[8], br[8];
            *(float4*)&ar[0] = *(float4*)&As[k * 128 + ty * 8];
            *(float4*)&ar[4] = *(float4*)&As[k * 128 + ty * 8 + 4];
            *(float4*)&br[0] = *(float4*)&Bs[k * 128 + tx * 8];
            *(float4*)&br[4] = *(float4*)&Bs[k * 128 + tx * 8 + 4];
#pragma unroll
            for (int i = 0; i < 8; i++)
#pragma unroll
                for (int j = 0; j < 8; j++) acc[i][j] += ar[i] * br[j];
        }
    }

    float bb[8];
#pragma unroll
    for (int j = 0; j < 8; j++) bb[j] = bias[ncol0 + tx * 8 + j];

#pragma unroll
    for (int i = 0; i < 8; i++) {
        const int row = bm * 128 + ty * 8 + i;
        float* dst = &g_P[(size_t)row * PCOLS + bn * 128 + tx * 8];
        float4 c0, c1;
        c0.x = acc[i][0] + bb[0]; c0.y = acc[i][1] + bb[1];
        c0.z = acc[i][2] + bb[2]; c0.w = acc[i][3] + bb[3];
        c1.x = acc[i][4] + bb[4]; c1.y = acc[i][5] + bb[5];
        c1.z = acc[i][6] + bb[6]; c1.w = acc[i][7] + bb[7];
        *(float4*)&dst[0] = c0;
        *(float4*)&dst[4] = c1;
    }
}

// ---------------------------------------------------------------------------
// Kernel 2: M partials. M[b,h] = lk1[b,h]^T @ lk1[b,h]  (64x64), split over 8
// sequence chunks for parallelism. grid = (16 bh, 8 parts), 256 threads.
// ---------------------------------------------------------------------------
__global__ __launch_bounds__(256) void compute_M_part() {
    __shared__ float Ls[64 * 68];
    const int bh = blockIdx.x;       // b*8 + h
    const int b  = bh >> 3;
    const int h  = bh & 7;
    const int part = blockIdx.y;
    const int tid = threadIdx.x;
    const int e  = tid & 63;
    const int d0 = tid >> 6;

    float acc[16];
#pragma unroll
    for (int i = 0; i < 16; i++) acc[i] = 0.f;

    const int colbase = 2048 + h * 64;   // LK1 columns
    for (int t = 0; t < 4; t++) {
        const int s0 = (part * 4 + t) * 64;
        __syncthreads();
#pragma unroll
        for (int ch = 0; ch < 4; ch++) {
            int idx = tid + 256 * ch;
            int r = idx >> 4, c4 = (idx & 15) * 4;
            *(float4*)&Ls[r * 68 + c4] =
                *(const float4*)&g_P[(size_t)(b * SEQ + s0 + r) * PCOLS + colbase + c4];
        }
        __syncthreads();
        for (int r = 0; r < 64; r++) {
            const float le = Ls[r * 68 + e];
#pragma unroll
            for (int i = 0; i < 16; i++)
                acc[i] += Ls[r * 68 + d0 + 4 * i] * le;
        }
    }
#pragma unroll
    for (int i = 0; i < 16; i++)
        g_Mpart[((size_t)part * 16 + bh) * 4096 + (d0 + 4 * i) * 64 + e] = acc[i];
}

// Kernel 2b: deterministic fixed-order reduce of the 8 partials.
__global__ __launch_bounds__(256) void reduce_M() {
    const int t = blockIdx.x * 256 + threadIdx.x;   // 0 .. 65535
    const int bh  = t >> 12;
    const int idx = t & 4095;
    float s = 0.f;
#pragma unroll
    for (int p = 0; p < 8; p++)
        s += g_Mpart[((size_t)p * 16 + bh) * 4096 + idx];
    g_M[(size_t)bh * 4096 + idx] = s;
}

// ---------------------------------------------------------------------------
// Kernel 3: LQ' = LQ @ M, in place over the LQ columns of g_P.
// grid = (64 row-blocks of 64, 8 heads), 256 threads.
// ---------------------------------------------------------------------------
__global__ __launch_bounds__(256) void lq_update() {
    __shared__ float Ms[64 * 65];
    __shared__ float Ls[64 * 68];
    const int rb = blockIdx.x;
    const int h  = blockIdx.y;
    const int row0 = rb * 64;
    const int b = row0 >> 11;            // /2048
    const int bh = b * 8 + h;
    const int tid = threadIdx.x;
    const int colbase = 1536 + h * 64;   // LQ columns

#pragma unroll
    for (int ch = 0; ch < 16; ch++) {
        int idx = tid + 256 * ch;
        int d = idx >> 6, e = idx & 63;
        Ms[d * 65 + e] = g_M[(size_t)bh * 4096 + idx];
    }
#pragma unroll
    for (int ch = 0; ch < 4; ch++) {
        int idx = tid + 256 * ch;
        int r = idx >> 4, c4 = (idx & 15) * 4;
        *(float4*)&Ls[r * 68 + c4] =
            *(const float4*)&g_P[(size_t)(row0 + r) * PCOLS + colbase + c4];
    }
    __syncthreads();

    const int e  = tid & 63;
    const int r0 = tid >> 6;
    float acc[16];
#pragma unroll
    for (int i = 0; i < 16; i++) acc[i] = 0.f;
    for (int d = 0; d < 64; d++) {
        const float mv = Ms[d * 65 + e];
#pragma unroll
        for (int i = 0; i < 16; i++)
            acc[i] += Ls[(r0 + 4 * i) * 68 + d] * mv;
    }
#pragma unroll
    for (int i = 0; i < 16; i++)
        g_P[(size_t)(row0 + r0 + 4 * i) * PCOLS + colbase + e] = acc[i];
}

// ---------------------------------------------------------------------------
// Kernel 4: flash attention (both branches).
// grid = (32 q-blocks, B*16 head-slots). BM=BN=64, 256 threads, 4x4 microtile.
// ---------------------------------------------------------------------------
__global__ __launch_bounds__(256) void flash_attn(const float* __restrict__ mask,
                                                  float* __restrict__ out) {
    extern __shared__ float sm[];
    float* Qs = sm;                    // 64*68
    float* Ks = sm + 64 * 68;
    float* Vs = sm + 2 * 64 * 68;
    float* Ps = sm + 3 * 64 * 68;

    const int tid = threadIdx.x;
    const int tx = tid & 15;
    const int ty = tid >> 4;
    const int qb = blockIdx.x;
    const int by = blockIdx.y;
    const int b = by >> 4;
    const int head = by & 15;
    const bool isloc = head >= 8;
    const int lh = head & 7;
    const int qcol  = isloc ? (1536 + lh * 64) : (head * 64);
    const int kcol  = isloc ? (2560 + lh * 64) : (512 + head * 64);
    const int vcol1 = isloc ? (3072 + lh * 64) : (1024 + head * 64);
    const int vcol2 = 3584 + lh * 64;
    const float scale = 0.125f;        // 1/sqrt(64)
    const int rowbase = b * SEQ;

    // Load Q tile
#pragma unroll
    for (int ch = 0; ch < 4; ch++) {
        int idx = tid + 256 * ch;
        int r = idx >> 4, c4 = (idx & 15) * 4;
        *(float4*)&Qs[r * 68 + c4] =
            *(const float4*)&g_P[(size_t)(rowbase + qb * 64 + r) * PCOLS + qcol + c4];
    }

    float o[4][4];
    float m[4], l[4];
#pragma unroll
    for (int i = 0; i < 4; i++) {
        m[i] = -1e30f; l[i] = 0.f;
#pragma unroll
        for (int j = 0; j < 4; j++) o[i][j] = 0.f;
    }

    for (int kt = 0; kt < 32; kt++) {
        __syncthreads();   // prior-iter Ps/Vs reads finished
#pragma unroll
        for (int ch = 0; ch < 4; ch++) {
            int idx = tid + 256 * ch;
            int r = idx >> 4, c4 = (idx & 15) * 4;
            size_t grow = (size_t)(rowbase + kt * 64 + r) * PCOLS;
            *(float4*)&Ks[r * 68 + c4] = *(const float4*)&g_P[grow + kcol + c4];
            float4 v1 = *(const float4*)&g_P[grow + vcol1 + c4];
            if (isloc) {
                float4 v2 = *(const float4*)&g_P[grow + vcol2 + c4];
                v1.x += v2.x; v1.y += v2.y; v1.z += v2.z; v1.w += v2.w;
            }
            *(float4*)&Vs[r * 68 + c4] = v1;
        }
        __syncthreads();

        // S tile: s[i][j] = Q[ty*4+i,:] . K[tx*4+j,:]
        float s[4][4];
#pragma unroll
        for (int i = 0; i < 4; i++)
#pragma unroll
            for (int j = 0; j < 4; j++) s[i][j] = 0.f;
#pragma unroll
        for (int k4 = 0; k4 < 64; k4 += 4) {
            float4 qv[4], kv[4];
#pragma unroll
            for (int i = 0; i < 4; i++)
                qv[i] = *(float4*)&Qs[(ty * 4 + i) * 68 + k4];
#pragma unroll
            for (int j = 0; j < 4; j++)
                kv[j] = *(float4*)&Ks[(tx * 4 + j) * 68 + k4];
#pragma unroll
            for (int i = 0; i < 4; i++)
#pragma unroll
                for (int j = 0; j < 4; j++) {
                    s[i][j] += qv[i].x * kv[j].x;
                    s[i][j] += qv[i].y * kv[j].y;
                    s[i][j] += qv[i].z * kv[j].z;
                    s[i][j] += qv[i].w * kv[j].w;
                }
        }

        float4 mk = make_float4(0.f, 0.f, 0.f, 0.f);
        if (!isloc)
            mk = *(const float4*)&mask[b * SEQ + kt * 64 + tx * 4];
#pragma unroll
        for (int i = 0; i < 4; i++) {
            s[i][0] = s[i][0] * scale + mk.x;
            s[i][1] = s[i][1] * scale + mk.y;
            s[i][2] = s[i][2] * scale + mk.z;
            s[i][3] = s[i][3] * scale + mk.w;
        }

        // online softmax (rows reduced across the 16 tx lanes)
#pragma unroll
        for (int i = 0; i < 4; i++) {
            float mx = fmaxf(fmaxf(s[i][0], s[i][1]), fmaxf(s[i][2], s[i][3]));
#pragma unroll
            for (int off = 1; off < 16; off <<= 1)
                mx = fmaxf(mx, __shfl_xor_sync(0xffffffffu, mx, off));
            const float mnew = fmaxf(m[i], mx);
            const float corr = __expf(m[i] - mnew);
            float ps = 0.f;
            float4 pv;
            pv.x = __expf(s[i][0] - mnew); ps += pv.x;
            pv.y = __expf(s[i][1] - mnew); ps += pv.y;
            pv.z = __expf(s[i][2] - mnew); ps += pv.z;
            pv.w = __expf(s[i][3] - mnew); ps += pv.w;
#pragma unroll
            for (int off = 1; off < 16; off <<= 1)
                ps += __shfl_xor_sync(0xffffffffu, ps, off);
            l[i] = l[i] * corr + ps;
            m[i] = mnew;
            o[i][0] *= corr; o[i][1] *= corr; o[i][2] *= corr; o[i][3] *= corr;
            *(float4*)&Ps[(ty * 4 + i) * 68 + tx * 4] = pv;
        }
        __syncthreads();

        // O += P @ V
        for (int jj = 0; jj < 64; jj++) {
            const float4 vv = *(float4*)&Vs[jj * 68 + tx * 4];
#pragma unroll
            for (int i = 0; i < 4; i++) {
                const float p = Ps[(ty * 4 + i) * 68 + jj];
                o[i][0] += p * vv.x;
                o[i][1] += p * vv.y;
                o[i][2] += p * vv.z;
                o[i][3] += p * vv.w;
            }
        }
    }

    // epilogue
    const int ocol = head * 64 + tx * 4;
#pragma unroll
    for (int i = 0; i < 4; i++) {
        const float inv = 1.0f / l[i];
        const int row = rowbase + qb * 64 + ty * 4 + i;
        float4 ov = make_float4(o[i][0] * inv, o[i][1] * inv, o[i][2] * inv, o[i][3] * inv);
        *(float4*)&out[(size_t)row * HID + ocol] = ov;
    }
}

// ---------------------------------------------------------------------------
extern "C" void kernel_launch(void* const* d_in, const int* in_sizes, int n_in,
                              void* d_out, int out_size) {
    (void)in_sizes; (void)n_in; (void)out_size;
    const float* X    = (const float*)d_in[0];
    const float* mask = (const float*)d_in[1];
    ProjArgs pa;
    for (int i = 0; i < 8; i++) {
        pa.w[i] = (const float*)d_in[2 + 2 * i];
        pa.b[i] = (const float*)d_in[3 + 2 * i];
    }
    float* out = (float*)d_out;

    const int FLASH_SMEM = 4 * 64 * 68 * (int)sizeof(float);   // 69632 B
    cudaFuncSetAttribute(flash_attn, cudaFuncAttributeMaxDynamicSharedMemorySize, FLASH_SMEM);

    proj_gemm<<<dim3(32, 32), 256>>>(X, pa);
    compute_M_part<<<dim3(16, 8), 256>>>();
    reduce_M<<<256, 256>>>();
    lq_update<<<dim3(64, 8), 256>>>();
    flash_attn<<<dim3(32, 32), 256, FLASH_SMEM>>>(mask, out);
}

// round 4
// speedup vs baseline: 3.2274x; 3.2274x over previous
#include <cuda_runtime.h>
#include <cuda_bf16.h>
#include <cstdint>

#define SEQ 2048
#define NROWS 4096
#define HID 1024
#define GC 1536   // global proj cols: Q 0, K 512, V 1024
#define LC 2560   // local proj cols: LQ 0, LK1 512, LK2 1024, LV1 1536, LV2 2048

__device__ __nv_bfloat16 g_Xh[(size_t)NROWS * HID];
__device__ __nv_bfloat16 g_Xl[(size_t)NROWS * HID];
__device__ __nv_bfloat16 g_Wth[(size_t)4096 * HID];   // all 8 W, transposed [n][k]
__device__ __nv_bfloat16 g_Wtl[(size_t)4096 * HID];
__device__ float g_bias[4096];
__device__ __nv_bfloat16 g_Pg[(size_t)NROWS * GC];    // global projections bf16
__device__ float g_Pf[(size_t)NROWS * LC];            // local projections fp32
__device__ float g_Mpart[8 * 16 * 64 * 64];
__device__ float g_M[16 * 64 * 64];

struct ProjArgs { const float* w[8]; const float* b[8]; };

// ---------------- helpers ----------------
__device__ __forceinline__ uint32_t cvta_s(const void* p) {
    return (uint32_t)__cvta_generic_to_shared(p);
}
__device__ __forceinline__ void ldsm_x4(uint32_t r[4], uint32_t a) {
    asm volatile("ldmatrix.sync.aligned.m8n8.x4.shared.b16 {%0,%1,%2,%3}, [%4];"
                 : "=r"(r[0]), "=r"(r[1]), "=r"(r[2]), "=r"(r[3]) : "r"(a));
}
__device__ __forceinline__ void ldsm_x2(uint32_t r[2], uint32_t a) {
    asm volatile("ldmatrix.sync.aligned.m8n8.x2.shared.b16 {%0,%1}, [%2];"
                 : "=r"(r[0]), "=r"(r[1]) : "r"(a));
}
__device__ __forceinline__ void ldsm_x2t(uint32_t r[2], uint32_t a) {
    asm volatile("ldmatrix.sync.aligned.m8n8.x2.trans.shared.b16 {%0,%1}, [%2];"
                 : "=r"(r[0]), "=r"(r[1]) : "r"(a));
}
__device__ __forceinline__ void mma_bf16(float c[4], const uint32_t a[4], const uint32_t b[2]) {
    asm volatile("mma.sync.aligned.m16n8k16.row.col.f32.bf16.bf16.f32 "
                 "{%0,%1,%2,%3},{%4,%5,%6,%7},{%8,%9},{%0,%1,%2,%3};"
                 : "+f"(c[0]), "+f"(c[1]), "+f"(c[2]), "+f"(c[3])
                 : "r"(a[0]), "r"(a[1]), "r"(a[2]), "r"(a[3]), "r"(b[0]), "r"(b[1]));
}
__device__ __forceinline__ void mma_tf32(float c[4], const uint32_t a[4], uint32_t b0, uint32_t b1) {
    asm volatile("mma.sync.aligned.m16n8k8.row.col.f32.tf32.tf32.f32 "
                 "{%0,%1,%2,%3},{%4,%5,%6,%7},{%8,%9},{%0,%1,%2,%3};"
                 : "+f"(c[0]), "+f"(c[1]), "+f"(c[2]), "+f"(c[3])
                 : "r"(a[0]), "r"(a[1]), "r"(a[2]), "r"(a[3]), "r"(b0), "r"(b1));
}
__device__ __forceinline__ uint32_t tf32_rna(float x) {
    uint32_t y; asm("cvt.rna.tf32.f32 %0, %1;" : "=r"(y) : "f"(x)); return y;
}
__device__ __forceinline__ void split2(float x, __nv_bfloat16& h, __nv_bfloat16& l) {
    h = __float2bfloat16_rn(x);
    l = __float2bfloat16_rn(x - __bfloat162float(h));
}
__device__ __forceinline__ uint32_t pack_bf16(float a, float b) {
    __nv_bfloat162 t = __floats2bfloat162_rn(a, b);
    return *(uint32_t*)&t;
}
__device__ __forceinline__ void pack_hl(float a, float b, uint32_t& h, uint32_t& l) {
    __nv_bfloat162 hh = __floats2bfloat162_rn(a, b);
    __nv_bfloat162 ll = __floats2bfloat162_rn(a - __bfloat162float(hh.x),
                                              b - __bfloat162float(hh.y));
    h = *(uint32_t*)&hh; l = *(uint32_t*)&ll;
}

// ---------------- prep kernels ----------------
__global__ void split_X(const float* __restrict__ X) {
    int t = blockIdx.x * 256 + threadIdx.x;               // 4096*1024/4 elems of 4
    float4 v = *(const float4*)&X[(size_t)t * 4];
    __nv_bfloat16 h, l;
    split2(v.x, h, l); g_Xh[(size_t)t*4+0] = h; g_Xl[(size_t)t*4+0] = l;
    split2(v.y, h, l); g_Xh[(size_t)t*4+1] = h; g_Xl[(size_t)t*4+1] = l;
    split2(v.z, h, l); g_Xh[(size_t)t*4+2] = h; g_Xl[(size_t)t*4+2] = l;
    split2(v.w, h, l); g_Xh[(size_t)t*4+3] = h; g_Xl[(size_t)t*4+3] = l;
}

__global__ void transW(ProjArgs pa) {
    __shared__ float tile[32][33];
    const int nb = blockIdx.x, kb = blockIdx.y, w = blockIdx.z;
    const float* __restrict__ W = pa.w[w];
    const int tx = threadIdx.x & 31, ty0 = threadIdx.x >> 5;
#pragma unroll
    for (int i = 0; i < 4; i++) {
        int ty = ty0 + 8 * i;
        tile[ty][tx] = W[(size_t)(kb * 32 + ty) * 512 + nb * 32 + tx];
    }
    __syncthreads();
#pragma unroll
    for (int i = 0; i < 4; i++) {
        int ty = ty0 + 8 * i;
        __nv_bfloat16 h, l; split2(tile[tx][ty], h, l);
        size_t o = (size_t)(w * 512 + nb * 32 + ty) * HID + kb * 32 + tx;
        g_Wth[o] = h; g_Wtl[o] = l;
    }
}

__global__ void bias_cat(ProjArgs pa) {
    int t = blockIdx.x * 256 + threadIdx.x;
    g_bias[t] = pa.b[t >> 9][t & 511];
}

// ---------------- projection GEMM (bf16 mma, 3-term for local) ----------------
__global__ __launch_bounds__(256) void proj_mma() {
    __shared__ __nv_bfloat16 Ah[128 * 40], Al[128 * 40], Bh[128 * 40], Bl[128 * 40];
    __shared__ float sbias[128];
    const int bm = blockIdx.y, bn = blockIdx.x;
    const int tid = threadIdx.x, lane = tid & 31, warp = tid >> 5;
    const int wr = warp >> 1, wc = warp & 1;
    const int g = lane >> 2, tig = lane & 3;
    const bool three = (bn >= 12);
    if (tid < 128) sbias[tid] = g_bias[bn * 128 + tid];

    float c[2][8][4];
#pragma unroll
    for (int mf = 0; mf < 2; mf++)
#pragma unroll
        for (int nf = 0; nf < 8; nf++)
#pragma unroll
            for (int i = 0; i < 4; i++) c[mf][nf][i] = 0.f;

    for (int k0 = 0; k0 < HID; k0 += 32) {
        __syncthreads();
#pragma unroll
        for (int i = 0; i < 2; i++) {
            int idx = tid + 256 * i;
            int r = idx >> 2, ch = idx & 3;
            size_t ga = (size_t)(bm * 128 + r) * HID + k0 + ch * 8;
            size_t gb = (size_t)(bn * 128 + r) * HID + k0 + ch * 8;
            *(uint4*)&Ah[r * 40 + ch * 8] = *(const uint4*)&g_Xh[ga];
            *(uint4*)&Bh[r * 40 + ch * 8] = *(const uint4*)&g_Wth[gb];
            if (three) {
                *(uint4*)&Al[r * 40 + ch * 8] = *(const uint4*)&g_Xl[ga];
                *(uint4*)&Bl[r * 40 + ch * 8] = *(const uint4*)&g_Wtl[gb];
            }
        }
        __syncthreads();

        uint32_t ah[2][2][4], al[2][2][4];
#pragma unroll
        for (int mf = 0; mf < 2; mf++)
#pragma unroll
            for (int ks = 0; ks < 2; ks++) {
                int row = wr * 32 + mf * 16 + (lane & 15);
                int col = ks * 16 + (lane >> 4) * 8;
                ldsm_x4(ah[mf][ks], cvta_s(&Ah[row * 40 + col]));
                if (three) ldsm_x4(al[mf][ks], cvta_s(&Al[row * 40 + col]));
            }
#pragma unroll
        for (int nf = 0; nf < 8; nf++) {
            uint32_t bh[2][2], bl[2][2];
#pragma unroll
            for (int ks = 0; ks < 2; ks++) {
                int row = wc * 64 + nf * 8 + (lane & 7);
                int col = ks * 16 + ((lane >> 3) & 1) * 8;
                ldsm_x2(bh[ks], cvta_s(&Bh[row * 40 + col]));
                if (three) ldsm_x2(bl[ks], cvta_s(&Bl[row * 40 + col]));
            }
#pragma unroll
            for (int mf = 0; mf < 2; mf++)
#pragma unroll
                for (int ks = 0; ks < 2; ks++) {
                    mma_bf16(c[mf][nf], ah[mf][ks], bh[ks]);
                    if (three) {
                        mma_bf16(c[mf][nf], al[mf][ks], bh[ks]);
                        mma_bf16(c[mf][nf], ah[mf][ks], bl[ks]);
                    }
                }
        }
    }

#pragma unroll
    for (int mf = 0; mf < 2; mf++)
#pragma unroll
        for (int nf = 0; nf < 8; nf++) {
            int lcol = wc * 64 + nf * 8 + 2 * tig;
            int gcol = bn * 128 + lcol;
            int r0 = bm * 128 + wr * 32 + mf * 16 + g;
            float v0 = c[mf][nf][0] + sbias[lcol];
            float v1 = c[mf][nf][1] + sbias[lcol + 1];
            float v2 = c[mf][nf][2] + sbias[lcol];
            float v3 = c[mf][nf][3] + sbias[lcol + 1];
            if (!three) {
                *(uint32_t*)&g_Pg[(size_t)r0 * GC + gcol]       = pack_bf16(v0, v1);
                *(uint32_t*)&g_Pg[(size_t)(r0 + 8) * GC + gcol] = pack_bf16(v2, v3);
            } else {
                int fc = gcol - GC;
                g_Pf[(size_t)r0 * LC + fc]           = v0;
                g_Pf[(size_t)r0 * LC + fc + 1]       = v1;
                g_Pf[(size_t)(r0 + 8) * LC + fc]     = v2;
                g_Pf[(size_t)(r0 + 8) * LC + fc + 1] = v3;
            }
        }
}

// ---------------- M = lk1^T lk1 (fp32) ----------------
__global__ __launch_bounds__(256) void compute_M_part() {
    __shared__ float Ls[64 * 68];
    const int bh = blockIdx.x, b = bh >> 3, h = bh & 7;
    const int part = blockIdx.y;
    const int tid = threadIdx.x, e = tid & 63, d0 = tid >> 6;
    float acc[16];
#pragma unroll
    for (int i = 0; i < 16; i++) acc[i] = 0.f;
    const int colbase = 512 + h * 64;
    for (int t = 0; t < 4; t++) {
        const int s0 = (part * 4 + t) * 64;
        __syncthreads();
#pragma unroll
        for (int ch = 0; ch < 4; ch++) {
            int idx = tid + 256 * ch;
            int r = idx >> 4, c4 = (idx & 15) * 4;
            *(float4*)&Ls[r * 68 + c4] =
                *(const float4*)&g_Pf[(size_t)(b * SEQ + s0 + r) * LC + colbase + c4];
        }
        __syncthreads();
        for (int r = 0; r < 64; r++) {
            float le = Ls[r * 68 + e];
#pragma unroll
            for (int i = 0; i < 16; i++)
                acc[i] += Ls[r * 68 + d0 + 4 * i] * le;
        }
    }
#pragma unroll
    for (int i = 0; i < 16; i++)
        g_Mpart[((size_t)part * 16 + bh) * 4096 + (d0 + 4 * i) * 64 + e] = acc[i];
}

__global__ __launch_bounds__(256) void reduce_M() {
    const int t = blockIdx.x * 256 + threadIdx.x;
    const int bh = t >> 12, idx = t & 4095;
    float s = 0.f;
#pragma unroll
    for (int p = 0; p < 8; p++) s += g_Mpart[((size_t)p * 16 + bh) * 4096 + idx];
    g_M[(size_t)bh * 4096 + idx] = s;
}

// ---------------- LQ' = LQ @ M (fp32, in place) ----------------
__global__ __launch_bounds__(256) void lq_update() {
    __shared__ float Ms[64 * 65];
    __shared__ float Ls[64 * 68];
    const int rb = blockIdx.x, h = blockIdx.y;
    const int row0 = rb * 64, b = row0 >> 11, bh = b * 8 + h;
    const int tid = threadIdx.x;
    const int colbase = h * 64;
#pragma unroll
    for (int ch = 0; ch < 16; ch++) {
        int idx = tid + 256 * ch;
        Ms[(idx >> 6) * 65 + (idx & 63)] = g_M[(size_t)bh * 4096 + idx];
    }
#pragma unroll
    for (int ch = 0; ch < 4; ch++) {
        int idx = tid + 256 * ch;
        int r = idx >> 4, c4 = (idx & 15) * 4;
        *(float4*)&Ls[r * 68 + c4] =
            *(const float4*)&g_Pf[(size_t)(row0 + r) * LC + colbase + c4];
    }
    __syncthreads();
    const int e = tid & 63, r0 = tid >> 6;
    float acc[16];
#pragma unroll
    for (int i = 0; i < 16; i++) acc[i] = 0.f;
    for (int d = 0; d < 64; d++) {
        float mv = Ms[d * 65 + e];
#pragma unroll
        for (int i = 0; i < 16; i++)
            acc[i] += Ls[(r0 + 4 * i) * 68 + d] * mv;
    }
#pragma unroll
    for (int i = 0; i < 16; i++)
        g_Pf[(size_t)(row0 + r0 + 4 * i) * LC + colbase + e] = acc[i];
}

// ---------------- global flash (bf16 mma), BM=128, 8 warps ----------------
__global__ __launch_bounds__(256) void flash_global(const float* __restrict__ mask,
                                                    float* __restrict__ out) {
    __shared__ __nv_bfloat16 Qs[128 * 72], Ks[64 * 72], Vs[64 * 72];
    __shared__ float maskS[2048];
    const int tid = threadIdx.x, lane = tid & 31, warp = tid >> 5;
    const int g = lane >> 2, tig = lane & 3;
    const int qb = blockIdx.x, by = blockIdx.y;
    const int b = by >> 3, h = by & 7;
    const int qcol = h * 64, kcol = 512 + h * 64, vcol = 1024 + h * 64;
    const int rowbase = b * SEQ;

#pragma unroll
    for (int i = 0; i < 8; i++) maskS[tid + 256 * i] = mask[b * SEQ + tid + 256 * i];
#pragma unroll
    for (int i = 0; i < 4; i++) {
        int idx = tid + 256 * i;
        int r = idx >> 3, ch = idx & 7;
        *(uint4*)&Qs[r * 72 + ch * 8] =
            *(const uint4*)&g_Pg[(size_t)(rowbase + qb * 128 + r) * GC + qcol + ch * 8];
    }
    __syncthreads();

    uint32_t qf[4][4];
#pragma unroll
    for (int ks = 0; ks < 4; ks++) {
        int row = warp * 16 + (lane & 15);
        int col = ks * 16 + (lane >> 4) * 8;
        ldsm_x4(qf[ks], cvta_s(&Qs[row * 72 + col]));
    }

    float of[8][4];
#pragma unroll
    for (int nf = 0; nf < 8; nf++)
#pragma unroll
        for (int i = 0; i < 4; i++) of[nf][i] = 0.f;
    float m0 = -1e30f, m1 = -1e30f, l0 = 0.f, l1 = 0.f;

    for (int kt = 0; kt < 32; kt++) {
        __syncthreads();
#pragma unroll
        for (int i = 0; i < 4; i++) {
            int idx = tid + 256 * i;
            int tz = idx >> 9, rc = idx & 511, r = rc >> 3, ch = rc & 7;
            size_t grow = (size_t)(rowbase + kt * 64 + r) * GC;
            __nv_bfloat16* dst = tz ? Vs : Ks;
            int col = tz ? vcol : kcol;
            *(uint4*)&dst[r * 72 + ch * 8] = *(const uint4*)&g_Pg[grow + col + ch * 8];
        }
        __syncthreads();

        float sf[8][4];
#pragma unroll
        for (int nf = 0; nf < 8; nf++) {
#pragma unroll
            for (int i = 0; i < 4; i++) sf[nf][i] = 0.f;
#pragma unroll
            for (int ks = 0; ks < 4; ks++) {
                uint32_t kb[2];
                int row = nf * 8 + (lane & 7);
                int col = ks * 16 + ((lane >> 3) & 1) * 8;
                ldsm_x2(kb, cvta_s(&Ks[row * 72 + col]));
                mma_bf16(sf[nf], qf[ks], kb);
            }
        }

        float mx0 = -1e30f, mx1 = -1e30f;
#pragma unroll
        for (int nf = 0; nf < 8; nf++) {
            float a0 = maskS[kt * 64 + nf * 8 + 2 * tig];
            float a1 = maskS[kt * 64 + nf * 8 + 2 * tig + 1];
            sf[nf][0] = sf[nf][0] * 0.125f + a0;
            sf[nf][1] = sf[nf][1] * 0.125f + a1;
            sf[nf][2] = sf[nf][2] * 0.125f + a0;
            sf[nf][3] = sf[nf][3] * 0.125f + a1;
            mx0 = fmaxf(mx0, fmaxf(sf[nf][0], sf[nf][1]));
            mx1 = fmaxf(mx1, fmaxf(sf[nf][2], sf[nf][3]));
        }
        mx0 = fmaxf(mx0, __shfl_xor_sync(~0u, mx0, 1));
        mx0 = fmaxf(mx0, __shfl_xor_sync(~0u, mx0, 2));
        mx1 = fmaxf(mx1, __shfl_xor_sync(~0u, mx1, 1));
        mx1 = fmaxf(mx1, __shfl_xor_sync(~0u, mx1, 2));
        float mn0 = fmaxf(m0, mx0), mn1 = fmaxf(m1, mx1);
        float cr0 = __expf(m0 - mn0), cr1 = __expf(m1 - mn1);
        m0 = mn0; m1 = mn1;

        float ps0 = 0.f, ps1 = 0.f;
        uint32_t pa[4][4];
#pragma unroll
        for (int nf = 0; nf < 8; nf++) {
            float p0 = __expf(sf[nf][0] - mn0), p1 = __expf(sf[nf][1] - mn0);
            float p2 = __expf(sf[nf][2] - mn1), p3 = __expf(sf[nf][3] - mn1);
            ps0 += p0 + p1; ps1 += p2 + p3;
            int ks = nf >> 1;
            if (nf & 1) { pa[ks][2] = pack_bf16(p0, p1); pa[ks][3] = pack_bf16(p2, p3); }
            else        { pa[ks][0] = pack_bf16(p0, p1); pa[ks][1] = pack_bf16(p2, p3); }
        }
        ps0 += __shfl_xor_sync(~0u, ps0, 1); ps0 += __shfl_xor_sync(~0u, ps0, 2);
        ps1 += __shfl_xor_sync(~0u, ps1, 1); ps1 += __shfl_xor_sync(~0u, ps1, 2);
        l0 = l0 * cr0 + ps0; l1 = l1 * cr1 + ps1;
#pragma unroll
        for (int nf = 0; nf < 8; nf++) {
            of[nf][0] *= cr0; of[nf][1] *= cr0; of[nf][2] *= cr1; of[nf][3] *= cr1;
        }
#pragma unroll
        for (int nf = 0; nf < 8; nf++)
#pragma unroll
            for (int ks = 0; ks < 4; ks++) {
                uint32_t vb[2];
                ldsm_x2t(vb, cvta_s(&Vs[(ks * 16 + (lane & 15)) * 72 + nf * 8]));
                mma_bf16(of[nf], pa[ks], vb);
            }
    }

    const float inv0 = 1.f / l0, inv1 = 1.f / l1;
    const int r0 = rowbase + qb * 128 + warp * 16 + g;
#pragma unroll
    for (int nf = 0; nf < 8; nf++) {
        int col = h * 64 + nf * 8 + 2 * tig;
        out[(size_t)r0 * HID + col]           = of[nf][0] * inv0;
        out[(size_t)r0 * HID + col + 1]       = of[nf][1] * inv0;
        out[(size_t)(r0 + 8) * HID + col]     = of[nf][2] * inv1;
        out[(size_t)(r0 + 8) * HID + col + 1] = of[nf][3] * inv1;
    }
}

// ---------------- local flash (tf32 2-term QK + split-bf16 PV), BM=64 ----------------
__global__ __launch_bounds__(128) void flash_local(float* __restrict__ out) {
    extern __shared__ char smraw[];
    float* Kh = (float*)smraw;                        // 64*68
    float* Kl = Kh + 64 * 68;
    __nv_bfloat16* Vh = (__nv_bfloat16*)(Kl + 64 * 68);   // 64*72
    __nv_bfloat16* Vl = Vh + 64 * 72;
    const int tid = threadIdx.x, lane = tid & 31, warp = tid >> 5;
    const int g = lane >> 2, tig = lane & 3;
    const int qb = blockIdx.x, by = blockIdx.y;
    const int b = by >> 3, h = by & 7;
    const int kcol = 1024 + h * 64, v1col = 1536 + h * 64, v2col = 2048 + h * 64;
    const int rowbase = b * SEQ;

    // Q fragments (tf32 hi/lo) straight from gmem
    uint32_t qh[8][4], ql[8][4];
    const int qr0 = rowbase + qb * 64 + warp * 16 + g;
#pragma unroll
    for (int ks = 0; ks < 8; ks++) {
        float a0 = g_Pf[(size_t)qr0 * LC + h * 64 + ks * 8 + tig];
        float a1 = g_Pf[(size_t)(qr0 + 8) * LC + h * 64 + ks * 8 + tig];
        float a2 = g_Pf[(size_t)qr0 * LC + h * 64 + ks * 8 + tig + 4];
        float a3 = g_Pf[(size_t)(qr0 + 8) * LC + h * 64 + ks * 8 + tig + 4];
        qh[ks][0] = tf32_rna(a0); ql[ks][0] = tf32_rna(a0 - __uint_as_float(qh[ks][0]));
        qh[ks][1] = tf32_rna(a1); ql[ks][1] = tf32_rna(a1 - __uint_as_float(qh[ks][1]));
        qh[ks][2] = tf32_rna(a2); ql[ks][2] = tf32_rna(a2 - __uint_as_float(qh[ks][2]));
        qh[ks][3] = tf32_rna(a3); ql[ks][3] = tf32_rna(a3 - __uint_as_float(qh[ks][3]));
    }

    float of[8][4];
#pragma unroll
    for (int nf = 0; nf < 8; nf++)
#pragma unroll
        for (int i = 0; i < 4; i++) of[nf][i] = 0.f;
    float m0 = -1e30f, m1 = -1e30f, l0 = 0.f, l1 = 0.f;

    for (int kt = 0; kt < 32; kt++) {
        __syncthreads();
#pragma unroll
        for (int i = 0; i < 8; i++) {
            int idx = tid + 128 * i;
            int r = idx >> 4, c4 = (idx & 15) * 4;
            size_t grow = (size_t)(rowbase + kt * 64 + r) * LC;
            float4 kv = *(const float4*)&g_Pf[grow + kcol + c4];
            uint32_t t;
            t = tf32_rna(kv.x); Kh[r*68+c4+0] = __uint_as_float(t); Kl[r*68+c4+0] = __uint_as_float(tf32_rna(kv.x - __uint_as_float(t)));
            t = tf32_rna(kv.y); Kh[r*68+c4+1] = __uint_as_float(t); Kl[r*68+c4+1] = __uint_as_float(tf32_rna(kv.y - __uint_as_float(t)));
            t = tf32_rna(kv.z); Kh[r*68+c4+2] = __uint_as_float(t); Kl[r*68+c4+2] = __uint_as_float(tf32_rna(kv.z - __uint_as_float(t)));
            t = tf32_rna(kv.w); Kh[r*68+c4+3] = __uint_as_float(t); Kl[r*68+c4+3] = __uint_as_float(tf32_rna(kv.w - __uint_as_float(t)));
            float4 v1 = *(const float4*)&g_Pf[grow + v1col + c4];
            float4 v2 = *(const float4*)&g_Pf[grow + v2col + c4];
            float s0 = v1.x + v2.x, s1 = v1.y + v2.y, s2 = v1.z + v2.z, s3 = v1.w + v2.w;
            __nv_bfloat16 hh, ll;
            split2(s0, hh, ll); Vh[r*72+c4+0] = hh; Vl[r*72+c4+0] = ll;
            split2(s1, hh, ll); Vh[r*72+c4+1] = hh; Vl[r*72+c4+1] = ll;
            split2(s2, hh, ll); Vh[r*72+c4+2] = hh; Vl[r*72+c4+2] = ll;
            split2(s3, hh, ll); Vh[r*72+c4+3] = hh; Vl[r*72+c4+3] = ll;
        }
        __syncthreads();

        float sf[8][4];
#pragma unroll
        for (int nf = 0; nf < 8; nf++) {
#pragma unroll
            for (int i = 0; i < 4; i++) sf[nf][i] = 0.f;
#pragma unroll
            for (int ks = 0; ks < 8; ks++) {
                int base = (nf * 8 + g) * 68 + ks * 8 + tig;
                uint32_t bh0 = __float_as_uint(Kh[base]);
                uint32_t bh1 = __float_as_uint(Kh[base + 4]);
                uint32_t bl0 = __float_as_uint(Kl[base]);
                uint32_t bl1 = __float_as_uint(Kl[base + 4]);
                mma_tf32(sf[nf], qh[ks], bh0, bh1);
                mma_tf32(sf[nf], ql[ks], bh0, bh1);
                mma_tf32(sf[nf], qh[ks], bl0, bl1);
            }
        }

        float mx0 = -1e30f, mx1 = -1e30f;
#pragma unroll
        for (int nf = 0; nf < 8; nf++) {
            sf[nf][0] *= 0.125f; sf[nf][1] *= 0.125f;
            sf[nf][2] *= 0.125f; sf[nf][3] *= 0.125f;
            mx0 = fmaxf(mx0, fmaxf(sf[nf][0], sf[nf][1]));
            mx1 = fmaxf(mx1, fmaxf(sf[nf][2], sf[nf][3]));
        }
        mx0 = fmaxf(mx0, __shfl_xor_sync(~0u, mx0, 1));
        mx0 = fmaxf(mx0, __shfl_xor_sync(~0u, mx0, 2));
        mx1 = fmaxf(mx1, __shfl_xor_sync(~0u, mx1, 1));
        mx1 = fmaxf(mx1, __shfl_xor_sync(~0u, mx1, 2));
        float mn0 = fmaxf(m0, mx0), mn1 = fmaxf(m1, mx1);
        float cr0 = __expf(m0 - mn0), cr1 = __expf(m1 - mn1);
        m0 = mn0; m1 = mn1;

        float ps0 = 0.f, ps1 = 0.f;
        uint32_t pah[4][4], pal[4][4];
#pragma unroll
        for (int nf = 0; nf < 8; nf++) {
            float p0 = __expf(sf[nf][0] - mn0), p1 = __expf(sf[nf][1] - mn0);
            float p2 = __expf(sf[nf][2] - mn1), p3 = __expf(sf[nf][3] - mn1);
            ps0 += p0 + p1; ps1 += p2 + p3;
            int ks = nf >> 1;
            if (nf & 1) { pack_hl(p0, p1, pah[ks][2], pal[ks][2]); pack_hl(p2, p3, pah[ks][3], pal[ks][3]); }
            else        { pack_hl(p0, p1, pah[ks][0], pal[ks][0]); pack_hl(p2, p3, pah[ks][1], pal[ks][1]); }
        }
        ps0 += __shfl_xor_sync(~0u, ps0, 1); ps0 += __shfl_xor_sync(~0u, ps0, 2);
        ps1 += __shfl_xor_sync(~0u, ps1, 1); ps1 += __shfl_xor_sync(~0u, ps1, 2);
        l0 = l0 * cr0 + ps0; l1 = l1 * cr1 + ps1;
#pragma unroll
        for (int nf = 0; nf < 8; nf++) {
            of[nf][0] *= cr0; of[nf][1] *= cr0; of[nf][2] *= cr1; of[nf][3] *= cr1;
        }
#pragma unroll
        for (int nf = 0; nf < 8; nf++)
#pragma unroll
            for (int ks = 0; ks < 4; ks++) {
                uint32_t vbh[2], vbl[2];
                ldsm_x2t(vbh, cvta_s(&Vh[(ks * 16 + (lane & 15)) * 72 + nf * 8]));
                ldsm_x2t(vbl, cvta_s(&Vl[(ks * 16 + (lane & 15)) * 72 + nf * 8]));
                mma_bf16(of[nf], pah[ks], vbh);
                mma_bf16(of[nf], pal[ks], vbh);
                mma_bf16(of[nf], pah[ks], vbl);
            }
    }

    const float inv0 = 1.f / l0, inv1 = 1.f / l1;
    const int r0 = rowbase + qb * 64 + warp * 16 + g;
#pragma unroll
    for (int nf = 0; nf < 8; nf++) {
        int col = (8 + h) * 64 + nf * 8 + 2 * tig;
        out[(size_t)r0 * HID + col]           = of[nf][0] * inv0;
        out[(size_t)r0 * HID + col + 1]       = of[nf][1] * inv0;
        out[(size_t)(r0 + 8) * HID + col]     = of[nf][2] * inv1;
        out[(size_t)(r0 + 8) * HID + col + 1] = of[nf][3] * inv1;
    }
}

// ---------------------------------------------------------------------------
extern "C" void kernel_launch(void* const* d_in, const int* in_sizes, int n_in,
                              void* d_out, int out_size) {
    (void)in_sizes; (void)n_in; (void)out_size;
    const float* X    = (const float*)d_in[0];
    const float* mask = (const float*)d_in[1];
    ProjArgs pa;
    for (int i = 0; i < 8; i++) {
        pa.w[i] = (const float*)d_in[2 + 2 * i];
        pa.b[i] = (const float*)d_in[3 + 2 * i];
    }
    float* out = (float*)d_out;

    const int LSMEM = (64 * 68 * 4) * 2 + (64 * 72 * 2) * 2;   // ~53.2 KB
    cudaFuncSetAttribute(flash_local, cudaFuncAttributeMaxDynamicSharedMemorySize, LSMEM);

    split_X<<<4096, 256>>>(X);
    transW<<<dim3(16, 32, 8), 256>>>(pa);
    bias_cat<<<16, 256>>>(pa);
    proj_mma<<<dim3(32, 32), 256>>>();
    compute_M_part<<<dim3(16, 8), 256>>>();
    reduce_M<<<256, 256>>>();
    lq_update<<<dim3(64, 8), 256>>>();
    flash_global<<<dim3(16, 16), 256>>>(mask, out);
    flash_local<<<dim3(32, 16), 128, LSMEM>>>(out);
}

// round 5
// speedup vs baseline: 3.5543x; 1.1013x over previous
#include <cuda_runtime.h>
#include <cuda_bf16.h>
#include <cstdint>

#define SEQ 2048
#define NROWS 4096
#define HID 1024
#define GC 1536   // global proj cols: Q 0, K 512, V 1024
#define LC 2560   // local proj cols: LQ 0, LK1 512, LK2 1024, LV1 1536, LV2 2048

__device__ __nv_bfloat16 g_Xh[(size_t)NROWS * HID];
__device__ __nv_bfloat16 g_Xl[(size_t)NROWS * HID];
__device__ __nv_bfloat16 g_Wth[(size_t)4096 * HID];   // all 8 W, transposed [n][k]
__device__ __nv_bfloat16 g_Wtl[(size_t)4096 * HID];
__device__ float g_bias[4096];
__device__ __nv_bfloat16 g_Pg[(size_t)NROWS * GC];    // global projections bf16
__device__ float g_Pf[(size_t)NROWS * LC];            // local projections fp32
__device__ float g_Mpart[8 * 16 * 64 * 64];
__device__ float g_M[16 * 64 * 64];
// precomputed flash_local operand planes
__device__ float g_K2h[(size_t)NROWS * 512];          // LK2 tf32-hi
__device__ float g_K2l[(size_t)NROWS * 512];          // LK2 tf32-lo
__device__ __nv_bfloat16 g_Vmh[(size_t)NROWS * 512];  // (LV1+LV2) bf16-hi
__device__ __nv_bfloat16 g_Vml[(size_t)NROWS * 512];  // (LV1+LV2) bf16-lo

struct ProjArgs { const float* w[8]; const float* b[8]; };

// ---------------- helpers ----------------
__device__ __forceinline__ uint32_t cvta_s(const void* p) {
    return (uint32_t)__cvta_generic_to_shared(p);
}
__device__ __forceinline__ void cp16(void* smem, const void* gmem) {
    asm volatile("cp.async.cg.shared.global [%0], [%1], 16;"
                 :: "r"(cvta_s(smem)), "l"(gmem));
}
__device__ __forceinline__ void ldsm_x4(uint32_t r[4], uint32_t a) {
    asm volatile("ldmatrix.sync.aligned.m8n8.x4.shared.b16 {%0,%1,%2,%3}, [%4];"
                 : "=r"(r[0]), "=r"(r[1]), "=r"(r[2]), "=r"(r[3]) : "r"(a));
}
__device__ __forceinline__ void ldsm_x2(uint32_t r[2], uint32_t a) {
    asm volatile("ldmatrix.sync.aligned.m8n8.x2.shared.b16 {%0,%1}, [%2];"
                 : "=r"(r[0]), "=r"(r[1]) : "r"(a));
}
__device__ __forceinline__ void ldsm_x2t(uint32_t r[2], uint32_t a) {
    asm volatile("ldmatrix.sync.aligned.m8n8.x2.trans.shared.b16 {%0,%1}, [%2];"
                 : "=r"(r[0]), "=r"(r[1]) : "r"(a));
}
__device__ __forceinline__ void mma_bf16(float c[4], const uint32_t a[4], const uint32_t b[2]) {
    asm volatile("mma.sync.aligned.m16n8k16.row.col.f32.bf16.bf16.f32 "
                 "{%0,%1,%2,%3},{%4,%5,%6,%7},{%8,%9},{%0,%1,%2,%3};"
                 : "+f"(c[0]), "+f"(c[1]), "+f"(c[2]), "+f"(c[3])
                 : "r"(a[0]), "r"(a[1]), "r"(a[2]), "r"(a[3]), "r"(b[0]), "r"(b[1]));
}
__device__ __forceinline__ void mma_tf32(float c[4], const uint32_t a[4], uint32_t b0, uint32_t b1) {
    asm volatile("mma.sync.aligned.m16n8k8.row.col.f32.tf32.tf32.f32 "
                 "{%0,%1,%2,%3},{%4,%5,%6,%7},{%8,%9},{%0,%1,%2,%3};"
                 : "+f"(c[0]), "+f"(c[1]), "+f"(c[2]), "+f"(c[3])
                 : "r"(a[0]), "r"(a[1]), "r"(a[2]), "r"(a[3]), "r"(b0), "r"(b1));
}
__device__ __forceinline__ uint32_t tf32_rna(float x) {
    uint32_t y; asm("cvt.rna.tf32.f32 %0, %1;" : "=r"(y) : "f"(x)); return y;
}
__device__ __forceinline__ void split2(float x, __nv_bfloat16& h, __nv_bfloat16& l) {
    h = __float2bfloat16_rn(x);
    l = __float2bfloat16_rn(x - __bfloat162float(h));
}
__device__ __forceinline__ uint32_t pack_bf16(float a, float b) {
    __nv_bfloat162 t = __floats2bfloat162_rn(a, b);
    return *(uint32_t*)&t;
}

// ---------------- prep kernels ----------------
__global__ void split_X(const float* __restrict__ X) {
    int t = blockIdx.x * 256 + threadIdx.x;
    float4 v = *(const float4*)&X[(size_t)t * 4];
    __nv_bfloat16 h, l;
    split2(v.x, h, l); g_Xh[(size_t)t*4+0] = h; g_Xl[(size_t)t*4+0] = l;
    split2(v.y, h, l); g_Xh[(size_t)t*4+1] = h; g_Xl[(size_t)t*4+1] = l;
    split2(v.z, h, l); g_Xh[(size_t)t*4+2] = h; g_Xl[(size_t)t*4+2] = l;
    split2(v.w, h, l); g_Xh[(size_t)t*4+3] = h; g_Xl[(size_t)t*4+3] = l;
}

__global__ void transW(ProjArgs pa) {
    __shared__ float tile[32][33];
    const int nb = blockIdx.x, kb = blockIdx.y, w = blockIdx.z;
    const float* __restrict__ W = pa.w[w];
    const int tx = threadIdx.x & 31, ty0 = threadIdx.x >> 5;
#pragma unroll
    for (int i = 0; i < 4; i++) {
        int ty = ty0 + 8 * i;
        tile[ty][tx] = W[(size_t)(kb * 32 + ty) * 512 + nb * 32 + tx];
    }
    __syncthreads();
#pragma unroll
    for (int i = 0; i < 4; i++) {
        int ty = ty0 + 8 * i;
        __nv_bfloat16 h, l; split2(tile[tx][ty], h, l);
        size_t o = (size_t)(w * 512 + nb * 32 + ty) * HID + kb * 32 + tx;
        g_Wth[o] = h; g_Wtl[o] = l;
    }
}

__global__ void bias_cat(ProjArgs pa) {
    int t = blockIdx.x * 256 + threadIdx.x;
    g_bias[t] = pa.b[t >> 9][t & 511];
}

// prep for flash_local: tf32 hi/lo LK2 planes + bf16 hi/lo merged-V planes
__global__ void prep_local() {
    int t = blockIdx.x * 256 + threadIdx.x;      // 4096*128
    int r = t >> 7, c4 = (t & 127) * 4;
    size_t grow = (size_t)r * LC;
    size_t po = (size_t)r * 512 + c4;
    float4 k = *(const float4*)&g_Pf[grow + 1024 + c4];
    float4 kh, kl;
    uint32_t u;
    u = tf32_rna(k.x); kh.x = __uint_as_float(u); kl.x = __uint_as_float(tf32_rna(k.x - kh.x));
    u = tf32_rna(k.y); kh.y = __uint_as_float(u); kl.y = __uint_as_float(tf32_rna(k.y - kh.y));
    u = tf32_rna(k.z); kh.z = __uint_as_float(u); kl.z = __uint_as_float(tf32_rna(k.z - kh.z));
    u = tf32_rna(k.w); kh.w = __uint_as_float(u); kl.w = __uint_as_float(tf32_rna(k.w - kh.w));
    *(float4*)&g_K2h[po] = kh;
    *(float4*)&g_K2l[po] = kl;
    float4 v1 = *(const float4*)&g_Pf[grow + 1536 + c4];
    float4 v2 = *(const float4*)&g_Pf[grow + 2048 + c4];
    float s0 = v1.x + v2.x, s1 = v1.y + v2.y, s2 = v1.z + v2.z, s3 = v1.w + v2.w;
    __nv_bfloat162 h01, h23, l01, l23;
    split2(s0, h01.x, l01.x); split2(s1, h01.y, l01.y);
    split2(s2, h23.x, l23.x); split2(s3, h23.y, l23.y);
    *(__nv_bfloat162*)&g_Vmh[po]     = h01;
    *(__nv_bfloat162*)&g_Vmh[po + 2] = h23;
    *(__nv_bfloat162*)&g_Vml[po]     = l01;
    *(__nv_bfloat162*)&g_Vml[po + 2] = l23;
}

// ---------------- projection GEMM (cp.async 2-stage pipeline) ----------------
__global__ __launch_bounds__(256) void proj_mma() {
    extern __shared__ char psmraw[];
    __nv_bfloat16* SB = (__nv_bfloat16*)psmraw;       // 8 planes of 5120 bf16
    float* sbias = (float*)(psmraw + 81920);
    const int bm = blockIdx.y, bn = blockIdx.x;
    const int tid = threadIdx.x, lane = tid & 31, warp = tid >> 5;
    const int wr = warp >> 1, wc = warp & 1;
    const int g = lane >> 2, tig = lane & 3;
    const bool three = (bn >= 12);
    if (tid < 128) sbias[tid] = g_bias[bn * 128 + tid];

    const int lr = tid >> 2, lch = tid & 3;

#define PL_AH(s) (SB + (s) * 5120)
#define PL_BH(s) (SB + 10240 + (s) * 5120)
#define PL_AL(s) (SB + 20480 + (s) * 5120)
#define PL_BL(s) (SB + 30720 + (s) * 5120)
#define ISSUE(kt, s) {                                                         \
        int k0 = (kt) * 32;                                                    \
        size_t ga0 = (size_t)(bm * 128 + lr) * HID + k0 + lch * 8;             \
        size_t gb0 = (size_t)(bn * 128 + lr) * HID + k0 + lch * 8;             \
        cp16(PL_AH(s) + lr * 40 + lch * 8,        g_Xh + ga0);                 \
        cp16(PL_AH(s) + (lr + 64) * 40 + lch * 8, g_Xh + ga0 + 64 * HID);      \
        cp16(PL_BH(s) + lr * 40 + lch * 8,        g_Wth + gb0);                \
        cp16(PL_BH(s) + (lr + 64) * 40 + lch * 8, g_Wth + gb0 + 64 * HID);     \
        if (three) {                                                           \
            cp16(PL_AL(s) + lr * 40 + lch * 8,        g_Xl + ga0);             \
            cp16(PL_AL(s) + (lr + 64) * 40 + lch * 8, g_Xl + ga0 + 64 * HID);  \
            cp16(PL_BL(s) + lr * 40 + lch * 8,        g_Wtl + gb0);            \
            cp16(PL_BL(s) + (lr + 64) * 40 + lch * 8, g_Wtl + gb0 + 64 * HID); \
        } }

    float c[2][8][4];
#pragma unroll
    for (int mf = 0; mf < 2; mf++)
#pragma unroll
        for (int nf = 0; nf < 8; nf++)
#pragma unroll
            for (int i = 0; i < 4; i++) c[mf][nf][i] = 0.f;

    ISSUE(0, 0);
    asm volatile("cp.async.commit_group;");

    for (int kt = 0; kt < 32; kt++) {
        const int s = kt & 1;
        if (kt + 1 < 32) { ISSUE(kt + 1, s ^ 1); }
        asm volatile("cp.async.commit_group;");
        asm volatile("cp.async.wait_group 1;");
        __syncthreads();

        __nv_bfloat16* Ah = PL_AH(s);
        __nv_bfloat16* Bh = PL_BH(s);
        __nv_bfloat16* Al = PL_AL(s);
        __nv_bfloat16* Bl = PL_BL(s);

        uint32_t ah[2][2][4], al[2][2][4];
#pragma unroll
        for (int mf = 0; mf < 2; mf++)
#pragma unroll
            for (int ks = 0; ks < 2; ks++) {
                int row = wr * 32 + mf * 16 + (lane & 15);
                int col = ks * 16 + (lane >> 4) * 8;
                ldsm_x4(ah[mf][ks], cvta_s(&Ah[row * 40 + col]));
                if (three) ldsm_x4(al[mf][ks], cvta_s(&Al[row * 40 + col]));
            }
#pragma unroll
        for (int nf = 0; nf < 8; nf++) {
            uint32_t bh[2][2], bl[2][2];
#pragma unroll
            for (int ks = 0; ks < 2; ks++) {
                int row = wc * 64 + nf * 8 + (lane & 7);
                int col = ks * 16 + ((lane >> 3) & 1) * 8;
                ldsm_x2(bh[ks], cvta_s(&Bh[row * 40 + col]));
                if (three) ldsm_x2(bl[ks], cvta_s(&Bl[row * 40 + col]));
            }
#pragma unroll
            for (int mf = 0; mf < 2; mf++)
#pragma unroll
                for (int ks = 0; ks < 2; ks++) {
                    mma_bf16(c[mf][nf], ah[mf][ks], bh[ks]);
                    if (three) {
                        mma_bf16(c[mf][nf], al[mf][ks], bh[ks]);
                        mma_bf16(c[mf][nf], ah[mf][ks], bl[ks]);
                    }
                }
        }
        __syncthreads();
    }

#pragma unroll
    for (int mf = 0; mf < 2; mf++)
#pragma unroll
        for (int nf = 0; nf < 8; nf++) {
            int lcol = wc * 64 + nf * 8 + 2 * tig;
            int gcol = bn * 128 + lcol;
            int r0 = bm * 128 + wr * 32 + mf * 16 + g;
            float v0 = c[mf][nf][0] + sbias[lcol];
            float v1 = c[mf][nf][1] + sbias[lcol + 1];
            float v2 = c[mf][nf][2] + sbias[lcol];
            float v3 = c[mf][nf][3] + sbias[lcol + 1];
            if (!three) {
                *(uint32_t*)&g_Pg[(size_t)r0 * GC + gcol]       = pack_bf16(v0, v1);
                *(uint32_t*)&g_Pg[(size_t)(r0 + 8) * GC + gcol] = pack_bf16(v2, v3);
            } else {
                int fc = gcol - GC;
                g_Pf[(size_t)r0 * LC + fc]           = v0;
                g_Pf[(size_t)r0 * LC + fc + 1]       = v1;
                g_Pf[(size_t)(r0 + 8) * LC + fc]     = v2;
                g_Pf[(size_t)(r0 + 8) * LC + fc + 1] = v3;
            }
        }
}

// ---------------- M = lk1^T lk1 (fp32) ----------------
__global__ __launch_bounds__(256) void compute_M_part() {
    __shared__ float Ls[64 * 68];
    const int bh = blockIdx.x, b = bh >> 3, h = bh & 7;
    const int part = blockIdx.y;
    const int tid = threadIdx.x, e = tid & 63, d0 = tid >> 6;
    float acc[16];
#pragma unroll
    for (int i = 0; i < 16; i++) acc[i] = 0.f;
    const int colbase = 512 + h * 64;
    for (int t = 0; t < 4; t++) {
        const int s0 = (part * 4 + t) * 64;
        __syncthreads();
#pragma unroll
        for (int ch = 0; ch < 4; ch++) {
            int idx = tid + 256 * ch;
            int r = idx >> 4, c4 = (idx & 15) * 4;
            *(float4*)&Ls[r * 68 + c4] =
                *(const float4*)&g_Pf[(size_t)(b * SEQ + s0 + r) * LC + colbase + c4];
        }
        __syncthreads();
        for (int r = 0; r < 64; r++) {
            float le = Ls[r * 68 + e];
#pragma unroll
            for (int i = 0; i < 16; i++)
                acc[i] += Ls[r * 68 + d0 + 4 * i] * le;
        }
    }
#pragma unroll
    for (int i = 0; i < 16; i++)
        g_Mpart[((size_t)part * 16 + bh) * 4096 + (d0 + 4 * i) * 64 + e] = acc[i];
}

__global__ __launch_bounds__(256) void reduce_M() {
    const int t = blockIdx.x * 256 + threadIdx.x;
    const int bh = t >> 12, idx = t & 4095;
    float s = 0.f;
#pragma unroll
    for (int p = 0; p < 8; p++) s += g_Mpart[((size_t)p * 16 + bh) * 4096 + idx];
    g_M[(size_t)bh * 4096 + idx] = s;
}

// ---------------- LQ' = LQ @ M (fp32, in place) ----------------
__global__ __launch_bounds__(256) void lq_update() {
    __shared__ float Ms[64 * 65];
    __shared__ float Ls[64 * 68];
    const int rb = blockIdx.x, h = blockIdx.y;
    const int row0 = rb * 64, b = row0 >> 11, bh = b * 8 + h;
    const int tid = threadIdx.x;
    const int colbase = h * 64;
#pragma unroll
    for (int ch = 0; ch < 16; ch++) {
        int idx = tid + 256 * ch;
        Ms[(idx >> 6) * 65 + (idx & 63)] = g_M[(size_t)bh * 4096 + idx];
    }
#pragma unroll
    for (int ch = 0; ch < 4; ch++) {
        int idx = tid + 256 * ch;
        int r = idx >> 4, c4 = (idx & 15) * 4;
        *(float4*)&Ls[r * 68 + c4] =
            *(const float4*)&g_Pf[(size_t)(row0 + r) * LC + colbase + c4];
    }
    __syncthreads();
    const int e = tid & 63, r0 = tid >> 6;
    float acc[16];
#pragma unroll
    for (int i = 0; i < 16; i++) acc[i] = 0.f;
    for (int d = 0; d < 64; d++) {
        float mv = Ms[d * 65 + e];
#pragma unroll
        for (int i = 0; i < 16; i++)
            acc[i] += Ls[(r0 + 4 * i) * 68 + d] * mv;
    }
#pragma unroll
    for (int i = 0; i < 16; i++)
        g_Pf[(size_t)(row0 + r0 + 4 * i) * LC + colbase + e] = acc[i];
}

// ---------------- global flash (bf16 mma), BM=128, 8 warps ----------------
__global__ __launch_bounds__(256) void flash_global(const float* __restrict__ mask,
                                                    float* __restrict__ out) {
    __shared__ __nv_bfloat16 Qs[128 * 72], Ks[64 * 72], Vs[64 * 72];
    __shared__ float maskS[2048];
    const int tid = threadIdx.x, lane = tid & 31, warp = tid >> 5;
    const int g = lane >> 2, tig = lane & 3;
    const int qb = blockIdx.x, by = blockIdx.y;
    const int b = by >> 3, h = by & 7;
    const int qcol = h * 64, kcol = 512 + h * 64, vcol = 1024 + h * 64;
    const int rowbase = b * SEQ;

#pragma unroll
    for (int i = 0; i < 8; i++) maskS[tid + 256 * i] = mask[b * SEQ + tid + 256 * i];
#pragma unroll
    for (int i = 0; i < 4; i++) {
        int idx = tid + 256 * i;
        int r = idx >> 3, ch = idx & 7;
        *(uint4*)&Qs[r * 72 + ch * 8] =
            *(const uint4*)&g_Pg[(size_t)(rowbase + qb * 128 + r) * GC + qcol + ch * 8];
    }
    __syncthreads();

    uint32_t qf[4][4];
#pragma unroll
    for (int ks = 0; ks < 4; ks++) {
        int row = warp * 16 + (lane & 15);
        int col = ks * 16 + (lane >> 4) * 8;
        ldsm_x4(qf[ks], cvta_s(&Qs[row * 72 + col]));
    }

    float of[8][4];
#pragma unroll
    for (int nf = 0; nf < 8; nf++)
#pragma unroll
        for (int i = 0; i < 4; i++) of[nf][i] = 0.f;
    float m0 = -1e30f, m1 = -1e30f, l0 = 0.f, l1 = 0.f;

    for (int kt = 0; kt < 32; kt++) {
        __syncthreads();
#pragma unroll
        for (int i = 0; i < 4; i++) {
            int idx = tid + 256 * i;
            int tz = idx >> 9, rc = idx & 511, r = rc >> 3, ch = rc & 7;
            size_t grow = (size_t)(rowbase + kt * 64 + r) * GC;
            __nv_bfloat16* dst = tz ? Vs : Ks;
            int col = tz ? vcol : kcol;
            *(uint4*)&dst[r * 72 + ch * 8] = *(const uint4*)&g_Pg[grow + col + ch * 8];
        }
        __syncthreads();

        float sf[8][4];
#pragma unroll
        for (int nf = 0; nf < 8; nf++) {
#pragma unroll
            for (int i = 0; i < 4; i++) sf[nf][i] = 0.f;
#pragma unroll
            for (int ks = 0; ks < 4; ks++) {
                uint32_t kb[2];
                int row = nf * 8 + (lane & 7);
                int col = ks * 16 + ((lane >> 3) & 1) * 8;
                ldsm_x2(kb, cvta_s(&Ks[row * 72 + col]));
                mma_bf16(sf[nf], qf[ks], kb);
            }
        }

        float mx0 = -1e30f, mx1 = -1e30f;
#pragma unroll
        for (int nf = 0; nf < 8; nf++) {
            float a0 = maskS[kt * 64 + nf * 8 + 2 * tig];
            float a1 = maskS[kt * 64 + nf * 8 + 2 * tig + 1];
            sf[nf][0] = sf[nf][0] * 0.125f + a0;
            sf[nf][1] = sf[nf][1] * 0.125f + a1;
            sf[nf][2] = sf[nf][2] * 0.125f + a0;
            sf[nf][3] = sf[nf][3] * 0.125f + a1;
            mx0 = fmaxf(mx0, fmaxf(sf[nf][0], sf[nf][1]));
            mx1 = fmaxf(mx1, fmaxf(sf[nf][2], sf[nf][3]));
        }
        mx0 = fmaxf(mx0, __shfl_xor_sync(~0u, mx0, 1));
        mx0 = fmaxf(mx0, __shfl_xor_sync(~0u, mx0, 2));
        mx1 = fmaxf(mx1, __shfl_xor_sync(~0u, mx1, 1));
        mx1 = fmaxf(mx1, __shfl_xor_sync(~0u, mx1, 2));
        float mn0 = fmaxf(m0, mx0), mn1 = fmaxf(m1, mx1);
        float cr0 = __expf(m0 - mn0), cr1 = __expf(m1 - mn1);
        m0 = mn0; m1 = mn1;

        float ps0 = 0.f, ps1 = 0.f;
        uint32_t pa[4][4];
#pragma unroll
        for (int nf = 0; nf < 8; nf++) {
            float p0 = __expf(sf[nf][0] - mn0), p1 = __expf(sf[nf][1] - mn0);
            float p2 = __expf(sf[nf][2] - mn1), p3 = __expf(sf[nf][3] - mn1);
            ps0 += p0 + p1; ps1 += p2 + p3;
            int ks = nf >> 1;
            if (nf & 1) { pa[ks][2] = pack_bf16(p0, p1); pa[ks][3] = pack_bf16(p2, p3); }
            else        { pa[ks][0] = pack_bf16(p0, p1); pa[ks][1] = pack_bf16(p2, p3); }
        }
        ps0 += __shfl_xor_sync(~0u, ps0, 1); ps0 += __shfl_xor_sync(~0u, ps0, 2);
        ps1 += __shfl_xor_sync(~0u, ps1, 1); ps1 += __shfl_xor_sync(~0u, ps1, 2);
        l0 = l0 * cr0 + ps0; l1 = l1 * cr1 + ps1;
#pragma unroll
        for (int nf = 0; nf < 8; nf++) {
            of[nf][0] *= cr0; of[nf][1] *= cr0; of[nf][2] *= cr1; of[nf][3] *= cr1;
        }
#pragma unroll
        for (int nf = 0; nf < 8; nf++)
#pragma unroll
            for (int ks = 0; ks < 4; ks++) {
                uint32_t vb[2];
                ldsm_x2t(vb, cvta_s(&Vs[(ks * 16 + (lane & 15)) * 72 + nf * 8]));
                mma_bf16(of[nf], pa[ks], vb);
            }
    }

    const float inv0 = 1.f / l0, inv1 = 1.f / l1;
    const int r0 = rowbase + qb * 128 + warp * 16 + g;
#pragma unroll
    for (int nf = 0; nf < 8; nf++) {
        int col = h * 64 + nf * 8 + 2 * tig;
        out[(size_t)r0 * HID + col]           = of[nf][0] * inv0;
        out[(size_t)r0 * HID + col + 1]       = of[nf][1] * inv0;
        out[(size_t)(r0 + 8) * HID + col]     = of[nf][2] * inv1;
        out[(size_t)(r0 + 8) * HID + col + 1] = of[nf][3] * inv1;
    }
}

// ---------------- local flash: BM=128, preconverted planes, 2-term PV ----------------
__global__ __launch_bounds__(256) void flash_local(float* __restrict__ out) {
    extern __shared__ char smraw[];
    float* Kh = (float*)smraw;                            // 64*68
    float* Kl = Kh + 64 * 68;
    __nv_bfloat16* Vh = (__nv_bfloat16*)(Kl + 64 * 68);   // 64*72
    __nv_bfloat16* Vl = Vh + 64 * 72;
    const int tid = threadIdx.x, lane = tid & 31, warp = tid >> 5;
    const int g = lane >> 2, tig = lane & 3;
    const int qb = blockIdx.x, by = blockIdx.y;
    const int b = by >> 3, h = by & 7;
    const int rowbase = b * SEQ;

    // Q fragments (tf32 hi/lo) straight from gmem fp32
    uint32_t qh[8][4], ql[8][4];
    const int qr0 = rowbase + qb * 128 + warp * 16 + g;
#pragma unroll
    for (int ks = 0; ks < 8; ks++) {
        float a0 = g_Pf[(size_t)qr0 * LC + h * 64 + ks * 8 + tig];
        float a1 = g_Pf[(size_t)(qr0 + 8) * LC + h * 64 + ks * 8 + tig];
        float a2 = g_Pf[(size_t)qr0 * LC + h * 64 + ks * 8 + tig + 4];
        float a3 = g_Pf[(size_t)(qr0 + 8) * LC + h * 64 + ks * 8 + tig + 4];
        qh[ks][0] = tf32_rna(a0); ql[ks][0] = tf32_rna(a0 - __uint_as_float(qh[ks][0]));
        qh[ks][1] = tf32_rna(a1); ql[ks][1] = tf32_rna(a1 - __uint_as_float(qh[ks][1]));
        qh[ks][2] = tf32_rna(a2); ql[ks][2] = tf32_rna(a2 - __uint_as_float(qh[ks][2]));
        qh[ks][3] = tf32_rna(a3); ql[ks][3] = tf32_rna(a3 - __uint_as_float(qh[ks][3]));
    }

    float of[8][4];
#pragma unroll
    for (int nf = 0; nf < 8; nf++)
#pragma unroll
        for (int i = 0; i < 4; i++) of[nf][i] = 0.f;
    float m0 = -1e30f, m1 = -1e30f, l0 = 0.f, l1 = 0.f;

    for (int kt = 0; kt < 32; kt++) {
        __syncthreads();
#pragma unroll
        for (int i = 0; i < 4; i++) {
            int idx = tid + 256 * i;
            int r = idx >> 4, c4 = (idx & 15) * 4;
            size_t go = (size_t)(rowbase + kt * 64 + r) * 512 + h * 64 + c4;
            *(float4*)&Kh[r * 68 + c4] = *(const float4*)&g_K2h[go];
            *(float4*)&Kl[r * 68 + c4] = *(const float4*)&g_K2l[go];
        }
#pragma unroll
        for (int i = 0; i < 2; i++) {
            int idx = tid + 256 * i;
            int r = idx >> 3, c8 = (idx & 7) * 8;
            size_t go = (size_t)(rowbase + kt * 64 + r) * 512 + h * 64 + c8;
            *(uint4*)&Vh[r * 72 + c8] = *(const uint4*)&g_Vmh[go];
            *(uint4*)&Vl[r * 72 + c8] = *(const uint4*)&g_Vml[go];
        }
        __syncthreads();

        float sf[8][4];
#pragma unroll
        for (int nf = 0; nf < 8; nf++) {
#pragma unroll
            for (int i = 0; i < 4; i++) sf[nf][i] = 0.f;
#pragma unroll
            for (int ks = 0; ks < 8; ks++) {
                int base = (nf * 8 + g) * 68 + ks * 8 + tig;
                uint32_t bh0 = __float_as_uint(Kh[base]);
                uint32_t bh1 = __float_as_uint(Kh[base + 4]);
                uint32_t bl0 = __float_as_uint(Kl[base]);
                uint32_t bl1 = __float_as_uint(Kl[base + 4]);
                mma_tf32(sf[nf], qh[ks], bh0, bh1);
                mma_tf32(sf[nf], ql[ks], bh0, bh1);
                mma_tf32(sf[nf], qh[ks], bl0, bl1);
            }
        }

        float mx0 = -1e30f, mx1 = -1e30f;
#pragma unroll
        for (int nf = 0; nf < 8; nf++) {
            sf[nf][0] *= 0.125f; sf[nf][1] *= 0.125f;
            sf[nf][2] *= 0.125f; sf[nf][3] *= 0.125f;
            mx0 = fmaxf(mx0, fmaxf(sf[nf][0], sf[nf][1]));
            mx1 = fmaxf(mx1, fmaxf(sf[nf][2], sf[nf][3]));
        }
        mx0 = fmaxf(mx0, __shfl_xor_sync(~0u, mx0, 1));
        mx0 = fmaxf(mx0, __shfl_xor_sync(~0u, mx0, 2));
        mx1 = fmaxf(mx1, __shfl_xor_sync(~0u, mx1, 1));
        mx1 = fmaxf(mx1, __shfl_xor_sync(~0u, mx1, 2));
        float mn0 = fmaxf(m0, mx0), mn1 = fmaxf(m1, mx1);
        float cr0 = __expf(m0 - mn0), cr1 = __expf(m1 - mn1);
        m0 = mn0; m1 = mn1;

        float ps0 = 0.f, ps1 = 0.f;
        uint32_t pah[4][4];
#pragma unroll
        for (int nf = 0; nf < 8; nf++) {
            float p0 = __expf(sf[nf][0] - mn0), p1 = __expf(sf[nf][1] - mn0);
            float p2 = __expf(sf[nf][2] - mn1), p3 = __expf(sf[nf][3] - mn1);
            ps0 += p0 + p1; ps1 += p2 + p3;
            int ks = nf >> 1;
            if (nf & 1) { pah[ks][2] = pack_bf16(p0, p1); pah[ks][3] = pack_bf16(p2, p3); }
            else        { pah[ks][0] = pack_bf16(p0, p1); pah[ks][1] = pack_bf16(p2, p3); }
        }
        ps0 += __shfl_xor_sync(~0u, ps0, 1); ps0 += __shfl_xor_sync(~0u, ps0, 2);
        ps1 += __shfl_xor_sync(~0u, ps1, 1); ps1 += __shfl_xor_sync(~0u, ps1, 2);
        l0 = l0 * cr0 + ps0; l1 = l1 * cr1 + ps1;
#pragma unroll
        for (int nf = 0; nf < 8; nf++) {
            of[nf][0] *= cr0; of[nf][1] *= cr0; of[nf][2] *= cr1; of[nf][3] *= cr1;
        }
#pragma unroll
        for (int nf = 0; nf < 8; nf++)
#pragma unroll
            for (int ks = 0; ks < 4; ks++) {
                uint32_t vbh[2], vbl[2];
                ldsm_x2t(vbh, cvta_s(&Vh[(ks * 16 + (lane & 15)) * 72 + nf * 8]));
                ldsm_x2t(vbl, cvta_s(&Vl[(ks * 16 + (lane & 15)) * 72 + nf * 8]));
                mma_bf16(of[nf], pah[ks], vbh);
                mma_bf16(of[nf], pah[ks], vbl);
            }
    }

    const float inv0 = 1.f / l0, inv1 = 1.f / l1;
    const int r0 = rowbase + qb * 128 + warp * 16 + g;
#pragma unroll
    for (int nf = 0; nf < 8; nf++) {
        int col = (8 + h) * 64 + nf * 8 + 2 * tig;
        out[(size_t)r0 * HID + col]           = of[nf][0] * inv0;
        out[(size_t)r0 * HID + col + 1]       = of[nf][1] * inv0;
        out[(size_t)(r0 + 8) * HID + col]     = of[nf][2] * inv1;
        out[(size_t)(r0 + 8) * HID + col + 1] = of[nf][3] * inv1;
    }
}

// ---------------------------------------------------------------------------
extern "C" void kernel_launch(void* const* d_in, const int* in_sizes, int n_in,
                              void* d_out, int out_size) {
    (void)in_sizes; (void)n_in; (void)out_size;
    const float* X    = (const float*)d_in[0];
    const float* mask = (const float*)d_in[1];
    ProjArgs pa;
    for (int i = 0; i < 8; i++) {
        pa.w[i] = (const float*)d_in[2 + 2 * i];
        pa.b[i] = (const float*)d_in[3 + 2 * i];
    }
    float* out = (float*)d_out;

    const int PSMEM = 81920 + 512;                             // 82432 B
    const int LSMEM = (64 * 68 * 4) * 2 + (64 * 72 * 2) * 2;   // 53248 B
    cudaFuncSetAttribute(proj_mma, cudaFuncAttributeMaxDynamicSharedMemorySize, PSMEM);
    cudaFuncSetAttribute(flash_local, cudaFuncAttributeMaxDynamicSharedMemorySize, LSMEM);

    split_X<<<4096, 256>>>(X);
    transW<<<dim3(16, 32, 8), 256>>>(pa);
    bias_cat<<<16, 256>>>(pa);
    proj_mma<<<dim3(32, 32), 256, PSMEM>>>();
    compute_M_part<<<dim3(16, 8), 256>>>();
    reduce_M<<<256, 256>>>();
    lq_update<<<dim3(64, 8), 256>>>();
    prep_local<<<2048, 256>>>();
    flash_global<<<dim3(16, 16), 256>>>(mask, out);
    flash_local<<<dim3(16, 16), 256, LSMEM>>>(out);
}

// round 6
// speedup vs baseline: 4.1491x; 1.1673x over previous
#include <cuda_runtime.h>
#include <cuda_bf16.h>
#include <cstdint>

#define SEQ 2048
#define NROWS 4096
#define HID 1024
#define GC 1536   // global proj cols: Q 0, K 512, V 1024
#define LC 2560   // local proj cols: LQ 0, LK1 512, LK2 1024, LV1 1536, LV2 2048

__device__ __nv_bfloat16 g_Xh[(size_t)NROWS * HID];
__device__ __nv_bfloat16 g_Xl[(size_t)NROWS * HID];
__device__ __nv_bfloat16 g_Wth[(size_t)4096 * HID];   // all 8 W, transposed [n][k]
__device__ __nv_bfloat16 g_Wtl[(size_t)4096 * HID];
__device__ float g_bias[4096];
__device__ __nv_bfloat16 g_Pg[(size_t)NROWS * GC];    // global projections bf16
__device__ float g_Pf[(size_t)NROWS * LC];            // local projections fp32
__device__ float g_Mpart[8 * 16 * 64 * 64];
__device__ float g_M[16 * 64 * 64];
// precomputed flash_local operand planes (bf16 hi/lo)
__device__ __nv_bfloat16 g_K2h[(size_t)NROWS * 512];
__device__ __nv_bfloat16 g_K2l[(size_t)NROWS * 512];
__device__ __nv_bfloat16 g_Vmh[(size_t)NROWS * 512];
__device__ __nv_bfloat16 g_Vml[(size_t)NROWS * 512];

struct ProjArgs { const float* w[8]; const float* b[8]; };

// ---------------- helpers ----------------
__device__ __forceinline__ uint32_t cvta_s(const void* p) {
    return (uint32_t)__cvta_generic_to_shared(p);
}
__device__ __forceinline__ void cp16(void* smem, const void* gmem) {
    asm volatile("cp.async.cg.shared.global [%0], [%1], 16;"
                 :: "r"(cvta_s(smem)), "l"(gmem));
}
__device__ __forceinline__ void ldsm_x4(uint32_t r[4], uint32_t a) {
    asm volatile("ldmatrix.sync.aligned.m8n8.x4.shared.b16 {%0,%1,%2,%3}, [%4];"
                 : "=r"(r[0]), "=r"(r[1]), "=r"(r[2]), "=r"(r[3]) : "r"(a));
}
__device__ __forceinline__ void ldsm_x2(uint32_t r[2], uint32_t a) {
    asm volatile("ldmatrix.sync.aligned.m8n8.x2.shared.b16 {%0,%1}, [%2];"
                 : "=r"(r[0]), "=r"(r[1]) : "r"(a));
}
__device__ __forceinline__ void ldsm_x2t(uint32_t r[2], uint32_t a) {
    asm volatile("ldmatrix.sync.aligned.m8n8.x2.trans.shared.b16 {%0,%1}, [%2];"
                 : "=r"(r[0]), "=r"(r[1]) : "r"(a));
}
__device__ __forceinline__ void mma_bf16(float c[4], const uint32_t a[4], const uint32_t b[2]) {
    asm volatile("mma.sync.aligned.m16n8k16.row.col.f32.bf16.bf16.f32 "
                 "{%0,%1,%2,%3},{%4,%5,%6,%7},{%8,%9},{%0,%1,%2,%3};"
                 : "+f"(c[0]), "+f"(c[1]), "+f"(c[2]), "+f"(c[3])
                 : "r"(a[0]), "r"(a[1]), "r"(a[2]), "r"(a[3]), "r"(b[0]), "r"(b[1]));
}
__device__ __forceinline__ void split2(float x, __nv_bfloat16& h, __nv_bfloat16& l) {
    h = __float2bfloat16_rn(x);
    l = __float2bfloat16_rn(x - __bfloat162float(h));
}
__device__ __forceinline__ uint32_t pack_bf16(float a, float b) {
    __nv_bfloat162 t = __floats2bfloat162_rn(a, b);
    return *(uint32_t*)&t;
}
__device__ __forceinline__ void pack_hl(float a, float b, uint32_t& h, uint32_t& l) {
    __nv_bfloat162 hh = __floats2bfloat162_rn(a, b);
    __nv_bfloat162 ll = __floats2bfloat162_rn(a - __bfloat162float(hh.x),
                                              b - __bfloat162float(hh.y));
    h = *(uint32_t*)&hh; l = *(uint32_t*)&ll;
}

// ---------------- prep kernels ----------------
__global__ void split_X(const float* __restrict__ X) {
    int t = blockIdx.x * 256 + threadIdx.x;
    float4 v = *(const float4*)&X[(size_t)t * 4];
    __nv_bfloat16 h, l;
    split2(v.x, h, l); g_Xh[(size_t)t*4+0] = h; g_Xl[(size_t)t*4+0] = l;
    split2(v.y, h, l); g_Xh[(size_t)t*4+1] = h; g_Xl[(size_t)t*4+1] = l;
    split2(v.z, h, l); g_Xh[(size_t)t*4+2] = h; g_Xl[(size_t)t*4+2] = l;
    split2(v.w, h, l); g_Xh[(size_t)t*4+3] = h; g_Xl[(size_t)t*4+3] = l;
}

__global__ void transW(ProjArgs pa) {
    __shared__ float tile[32][33];
    const int nb = blockIdx.x, kb = blockIdx.y, w = blockIdx.z;
    const float* __restrict__ W = pa.w[w];
    const int tx = threadIdx.x & 31, ty0 = threadIdx.x >> 5;
#pragma unroll
    for (int i = 0; i < 4; i++) {
        int ty = ty0 + 8 * i;
        tile[ty][tx] = W[(size_t)(kb * 32 + ty) * 512 + nb * 32 + tx];
    }
    __syncthreads();
#pragma unroll
    for (int i = 0; i < 4; i++) {
        int ty = ty0 + 8 * i;
        __nv_bfloat16 h, l; split2(tile[tx][ty], h, l);
        size_t o = (size_t)(w * 512 + nb * 32 + ty) * HID + kb * 32 + tx;
        g_Wth[o] = h; g_Wtl[o] = l;
    }
}

__global__ void bias_cat(ProjArgs pa) {
    int t = blockIdx.x * 256 + threadIdx.x;
    g_bias[t] = pa.b[t >> 9][t & 511];
}

// prep for flash_local: bf16 hi/lo LK2 planes + bf16 hi/lo merged-V planes
__global__ void prep_local() {
    int t = blockIdx.x * 256 + threadIdx.x;      // 4096*128
    int r = t >> 7, c4 = (t & 127) * 4;
    size_t grow = (size_t)r * LC;
    size_t po = (size_t)r * 512 + c4;
    float4 k = *(const float4*)&g_Pf[grow + 1024 + c4];
    __nv_bfloat162 h01, h23, l01, l23;
    split2(k.x, h01.x, l01.x); split2(k.y, h01.y, l01.y);
    split2(k.z, h23.x, l23.x); split2(k.w, h23.y, l23.y);
    *(__nv_bfloat162*)&g_K2h[po]     = h01;
    *(__nv_bfloat162*)&g_K2h[po + 2] = h23;
    *(__nv_bfloat162*)&g_K2l[po]     = l01;
    *(__nv_bfloat162*)&g_K2l[po + 2] = l23;
    float4 v1 = *(const float4*)&g_Pf[grow + 1536 + c4];
    float4 v2 = *(const float4*)&g_Pf[grow + 2048 + c4];
    split2(v1.x + v2.x, h01.x, l01.x); split2(v1.y + v2.y, h01.y, l01.y);
    split2(v1.z + v2.z, h23.x, l23.x); split2(v1.w + v2.w, h23.y, l23.y);
    *(__nv_bfloat162*)&g_Vmh[po]     = h01;
    *(__nv_bfloat162*)&g_Vmh[po + 2] = h23;
    *(__nv_bfloat162*)&g_Vml[po]     = l01;
    *(__nv_bfloat162*)&g_Vml[po + 2] = l23;
}

// ---------------- global projection GEMM (1-term, 3-stage pipeline) ----------------
__global__ __launch_bounds__(256, 2) void proj_g() {
    extern __shared__ char psg[];
    __nv_bfloat16* SB = (__nv_bfloat16*)psg;          // 3 stages x (A,B) 5120 bf16 each
    float* sbias = (float*)(psg + 61440);
    const int bm = blockIdx.y, bn = blockIdx.x;        // bn 0..11
    const int tid = threadIdx.x, lane = tid & 31, warp = tid >> 5;
    const int wr = warp >> 1, wc = warp & 1;
    const int g = lane >> 2, tig = lane & 3;
    if (tid < 128) sbias[tid] = g_bias[bn * 128 + tid];
    const int lr = tid >> 2, lch = tid & 3;

#define GP_A(s) (SB + (s) * 5120)
#define GP_B(s) (SB + 15360 + (s) * 5120)
#define GP_ISS(kt, s) {                                                        \
        int k0 = (kt) * 32;                                                    \
        size_t ga0 = (size_t)(bm * 128 + lr) * HID + k0 + lch * 8;             \
        size_t gb0 = (size_t)(bn * 128 + lr) * HID + k0 + lch * 8;             \
        cp16(GP_A(s) + lr * 40 + lch * 8,        g_Xh + ga0);                  \
        cp16(GP_A(s) + (lr + 64) * 40 + lch * 8, g_Xh + ga0 + 64 * HID);       \
        cp16(GP_B(s) + lr * 40 + lch * 8,        g_Wth + gb0);                 \
        cp16(GP_B(s) + (lr + 64) * 40 + lch * 8, g_Wth + gb0 + 64 * HID); }

    float c[2][8][4];
#pragma unroll
    for (int mf = 0; mf < 2; mf++)
#pragma unroll
        for (int nf = 0; nf < 8; nf++)
#pragma unroll
            for (int i = 0; i < 4; i++) c[mf][nf][i] = 0.f;

    GP_ISS(0, 0); asm volatile("cp.async.commit_group;");
    GP_ISS(1, 1); asm volatile("cp.async.commit_group;");

    for (int kt = 0; kt < 32; kt++) {
        const int s = kt % 3;
        asm volatile("cp.async.wait_group 1;");
        __syncthreads();
        if (kt + 2 < 32) { GP_ISS(kt + 2, (kt + 2) % 3); }
        asm volatile("cp.async.commit_group;");

        __nv_bfloat16* Ah = GP_A(s);
        __nv_bfloat16* Bh = GP_B(s);
        uint32_t ah[2][2][4];
#pragma unroll
        for (int mf = 0; mf < 2; mf++)
#pragma unroll
            for (int ks = 0; ks < 2; ks++) {
                int row = wr * 32 + mf * 16 + (lane & 15);
                int col = ks * 16 + (lane >> 4) * 8;
                ldsm_x4(ah[mf][ks], cvta_s(&Ah[row * 40 + col]));
            }
#pragma unroll
        for (int nf = 0; nf < 8; nf++) {
            uint32_t bh[2][2];
#pragma unroll
            for (int ks = 0; ks < 2; ks++) {
                int row = wc * 64 + nf * 8 + (lane & 7);
                int col = ks * 16 + ((lane >> 3) & 1) * 8;
                ldsm_x2(bh[ks], cvta_s(&Bh[row * 40 + col]));
            }
#pragma unroll
            for (int mf = 0; mf < 2; mf++)
#pragma unroll
                for (int ks = 0; ks < 2; ks++)
                    mma_bf16(c[mf][nf], ah[mf][ks], bh[ks]);
        }
    }

#pragma unroll
    for (int mf = 0; mf < 2; mf++)
#pragma unroll
        for (int nf = 0; nf < 8; nf++) {
            int lcol = wc * 64 + nf * 8 + 2 * tig;
            int gcol = bn * 128 + lcol;
            int r0 = bm * 128 + wr * 32 + mf * 16 + g;
            float v0 = c[mf][nf][0] + sbias[lcol];
            float v1 = c[mf][nf][1] + sbias[lcol + 1];
            float v2 = c[mf][nf][2] + sbias[lcol];
            float v3 = c[mf][nf][3] + sbias[lcol + 1];
            *(uint32_t*)&g_Pg[(size_t)r0 * GC + gcol]       = pack_bf16(v0, v1);
            *(uint32_t*)&g_Pg[(size_t)(r0 + 8) * GC + gcol] = pack_bf16(v2, v3);
        }
}

// ---------------- local projection GEMM (3-term, 2-stage pipeline) ----------------
__global__ __launch_bounds__(256) void proj_l() {
    extern __shared__ char psl[];
    __nv_bfloat16* SB = (__nv_bfloat16*)psl;
    float* sbias = (float*)(psl + 81920);
    const int bm = blockIdx.y, bn = blockIdx.x;        // bn 0..19
    const int tid = threadIdx.x, lane = tid & 31, warp = tid >> 5;
    const int wr = warp >> 1, wc = warp & 1;
    const int g = lane >> 2, tig = lane & 3;
    if (tid < 128) sbias[tid] = g_bias[GC + bn * 128 + tid];
    const int lr = tid >> 2, lch = tid & 3;

#define LP_AH(s) (SB + (s) * 5120)
#define LP_BH(s) (SB + 10240 + (s) * 5120)
#define LP_AL(s) (SB + 20480 + (s) * 5120)
#define LP_BL(s) (SB + 30720 + (s) * 5120)
#define LP_ISS(kt, s) {                                                        \
        int k0 = (kt) * 32;                                                    \
        size_t ga0 = (size_t)(bm * 128 + lr) * HID + k0 + lch * 8;             \
        size_t gb0 = (size_t)(GC + bn * 128 + lr) * HID + k0 + lch * 8;        \
        cp16(LP_AH(s) + lr * 40 + lch * 8,        g_Xh + ga0);                 \
        cp16(LP_AH(s) + (lr + 64) * 40 + lch * 8, g_Xh + ga0 + 64 * HID);      \
        cp16(LP_BH(s) + lr * 40 + lch * 8,        g_Wth + gb0);                \
        cp16(LP_BH(s) + (lr + 64) * 40 + lch * 8, g_Wth + gb0 + 64 * HID);     \
        cp16(LP_AL(s) + lr * 40 + lch * 8,        g_Xl + ga0);                 \
        cp16(LP_AL(s) + (lr + 64) * 40 + lch * 8, g_Xl + ga0 + 64 * HID);      \
        cp16(LP_BL(s) + lr * 40 + lch * 8,        g_Wtl + gb0);                \
        cp16(LP_BL(s) + (lr + 64) * 40 + lch * 8, g_Wtl + gb0 + 64 * HID); }

    float c[2][8][4];
#pragma unroll
    for (int mf = 0; mf < 2; mf++)
#pragma unroll
        for (int nf = 0; nf < 8; nf++)
#pragma unroll
            for (int i = 0; i < 4; i++) c[mf][nf][i] = 0.f;

    LP_ISS(0, 0); asm volatile("cp.async.commit_group;");

    for (int kt = 0; kt < 32; kt++) {
        const int s = kt & 1;
        if (kt + 1 < 32) { LP_ISS(kt + 1, s ^ 1); }
        asm volatile("cp.async.commit_group;");
        asm volatile("cp.async.wait_group 1;");
        __syncthreads();

        __nv_bfloat16* Ah = LP_AH(s);
        __nv_bfloat16* Bh = LP_BH(s);
        __nv_bfloat16* Al = LP_AL(s);
        __nv_bfloat16* Bl = LP_BL(s);
        uint32_t ah[2][2][4], al[2][2][4];
#pragma unroll
        for (int mf = 0; mf < 2; mf++)
#pragma unroll
            for (int ks = 0; ks < 2; ks++) {
                int row = wr * 32 + mf * 16 + (lane & 15);
                int col = ks * 16 + (lane >> 4) * 8;
                ldsm_x4(ah[mf][ks], cvta_s(&Ah[row * 40 + col]));
                ldsm_x4(al[mf][ks], cvta_s(&Al[row * 40 + col]));
            }
#pragma unroll
        for (int nf = 0; nf < 8; nf++) {
            uint32_t bh[2][2], bl[2][2];
#pragma unroll
            for (int ks = 0; ks < 2; ks++) {
                int row = wc * 64 + nf * 8 + (lane & 7);
                int col = ks * 16 + ((lane >> 3) & 1) * 8;
                ldsm_x2(bh[ks], cvta_s(&Bh[row * 40 + col]));
                ldsm_x2(bl[ks], cvta_s(&Bl[row * 40 + col]));
            }
#pragma unroll
            for (int mf = 0; mf < 2; mf++)
#pragma unroll
                for (int ks = 0; ks < 2; ks++) {
                    mma_bf16(c[mf][nf], ah[mf][ks], bh[ks]);
                    mma_bf16(c[mf][nf], al[mf][ks], bh[ks]);
                    mma_bf16(c[mf][nf], ah[mf][ks], bl[ks]);
                }
        }
        __syncthreads();
    }

#pragma unroll
    for (int mf = 0; mf < 2; mf++)
#pragma unroll
        for (int nf = 0; nf < 8; nf++) {
            int lcol = wc * 64 + nf * 8 + 2 * tig;
            int fc = bn * 128 + lcol;
            int r0 = bm * 128 + wr * 32 + mf * 16 + g;
            g_Pf[(size_t)r0 * LC + fc]           = c[mf][nf][0] + sbias[lcol];
            g_Pf[(size_t)r0 * LC + fc + 1]       = c[mf][nf][1] + sbias[lcol + 1];
            g_Pf[(size_t)(r0 + 8) * LC + fc]     = c[mf][nf][2] + sbias[lcol];
            g_Pf[(size_t)(r0 + 8) * LC + fc + 1] = c[mf][nf][3] + sbias[lcol + 1];
        }
}

// ---------------- M = lk1^T lk1 (fp32) ----------------
__global__ __launch_bounds__(256) void compute_M_part() {
    __shared__ float Ls[64 * 68];
    const int bh = blockIdx.x, b = bh >> 3, h = bh & 7;
    const int part = blockIdx.y;
    const int tid = threadIdx.x, e = tid & 63, d0 = tid >> 6;
    float acc[16];
#pragma unroll
    for (int i = 0; i < 16; i++) acc[i] = 0.f;
    const int colbase = 512 + h * 64;
    for (int t = 0; t < 4; t++) {
        const int s0 = (part * 4 + t) * 64;
        __syncthreads();
#pragma unroll
        for (int ch = 0; ch < 4; ch++) {
            int idx = tid + 256 * ch;
            int r = idx >> 4, c4 = (idx & 15) * 4;
            *(float4*)&Ls[r * 68 + c4] =
                *(const float4*)&g_Pf[(size_t)(b * SEQ + s0 + r) * LC + colbase + c4];
        }
        __syncthreads();
        for (int r = 0; r < 64; r++) {
            float le = Ls[r * 68 + e];
#pragma unroll
            for (int i = 0; i < 16; i++)
                acc[i] += Ls[r * 68 + d0 + 4 * i] * le;
        }
    }
#pragma unroll
    for (int i = 0; i < 16; i++)
        g_Mpart[((size_t)part * 16 + bh) * 4096 + (d0 + 4 * i) * 64 + e] = acc[i];
}

__global__ __launch_bounds__(256) void reduce_M() {
    const int t = blockIdx.x * 256 + threadIdx.x;
    const int bh = t >> 12, idx = t & 4095;
    float s = 0.f;
#pragma unroll
    for (int p = 0; p < 8; p++) s += g_Mpart[((size_t)p * 16 + bh) * 4096 + idx];
    g_M[(size_t)bh * 4096 + idx] = s;
}

// ---------------- LQ' = LQ @ M (fp32, in place) ----------------
__global__ __launch_bounds__(256) void lq_update() {
    __shared__ float Ms[64 * 65];
    __shared__ float Ls[64 * 68];
    const int rb = blockIdx.x, h = blockIdx.y;
    const int row0 = rb * 64, b = row0 >> 11, bh = b * 8 + h;
    const int tid = threadIdx.x;
    const int colbase = h * 64;
#pragma unroll
    for (int ch = 0; ch < 16; ch++) {
        int idx = tid + 256 * ch;
        Ms[(idx >> 6) * 65 + (idx & 63)] = g_M[(size_t)bh * 4096 + idx];
    }
#pragma unroll
    for (int ch = 0; ch < 4; ch++) {
        int idx = tid + 256 * ch;
        int r = idx >> 4, c4 = (idx & 15) * 4;
        *(float4*)&Ls[r * 68 + c4] =
            *(const float4*)&g_Pf[(size_t)(row0 + r) * LC + colbase + c4];
    }
    __syncthreads();
    const int e = tid & 63, r0 = tid >> 6;
    float acc[16];
#pragma unroll
    for (int i = 0; i < 16; i++) acc[i] = 0.f;
    for (int d = 0; d < 64; d++) {
        float mv = Ms[d * 65 + e];
#pragma unroll
        for (int i = 0; i < 16; i++)
            acc[i] += Ls[(r0 + 4 * i) * 68 + d] * mv;
    }
#pragma unroll
    for (int i = 0; i < 16; i++)
        g_Pf[(size_t)(row0 + r0 + 4 * i) * LC + colbase + e] = acc[i];
}

// ---------------- global flash: BM=128, cp.async double-buffered K/V ----------------
__global__ __launch_bounds__(256) void flash_global(const float* __restrict__ mask,
                                                    float* __restrict__ out) {
    extern __shared__ char gsm[];
    __nv_bfloat16* Qs = (__nv_bfloat16*)gsm;                 // 128*72
    float* maskS = (float*)(gsm + 18432);                    // 2048 floats
#define GF_K(s) ((__nv_bfloat16*)(gsm + 26624 + (s) * 18432))
#define GF_V(s) ((__nv_bfloat16*)(gsm + 26624 + (s) * 18432 + 9216))
    const int tid = threadIdx.x, lane = tid & 31, warp = tid >> 5;
    const int g = lane >> 2, tig = lane & 3;
    const int qb = blockIdx.x, by = blockIdx.y;
    const int b = by >> 3, h = by & 7;
    const int qcol = h * 64, kcol = 512 + h * 64, vcol = 1024 + h * 64;
    const int rowbase = b * SEQ;
    const int lr = tid >> 2, lch = tid & 3;

#define GF_ISS(kt, s) {                                                        \
        size_t grow = (size_t)(rowbase + (kt) * 64 + lr) * GC;                 \
        cp16(GF_K(s) + lr * 72 + lch * 16,     &g_Pg[grow + kcol + lch * 16]); \
        cp16(GF_K(s) + lr * 72 + lch * 16 + 8, &g_Pg[grow + kcol + lch * 16 + 8]); \
        cp16(GF_V(s) + lr * 72 + lch * 16,     &g_Pg[grow + vcol + lch * 16]); \
        cp16(GF_V(s) + lr * 72 + lch * 16 + 8, &g_Pg[grow + vcol + lch * 16 + 8]); }

#pragma unroll
    for (int i = 0; i < 8; i++) maskS[tid + 256 * i] = mask[b * SEQ + tid + 256 * i];
#pragma unroll
    for (int i = 0; i < 4; i++) {
        int idx = tid + 256 * i;
        int r = idx >> 3, ch = idx & 7;
        *(uint4*)&Qs[r * 72 + ch * 8] =
            *(const uint4*)&g_Pg[(size_t)(rowbase + qb * 128 + r) * GC + qcol + ch * 8];
    }
    GF_ISS(0, 0); asm volatile("cp.async.commit_group;");
    __syncthreads();

    uint32_t qf[4][4];
#pragma unroll
    for (int ks = 0; ks < 4; ks++) {
        int row = warp * 16 + (lane & 15);
        int col = ks * 16 + (lane >> 4) * 8;
        ldsm_x4(qf[ks], cvta_s(&Qs[row * 72 + col]));
    }

    float of[8][4];
#pragma unroll
    for (int nf = 0; nf < 8; nf++)
#pragma unroll
        for (int i = 0; i < 4; i++) of[nf][i] = 0.f;
    float m0 = -1e30f, m1 = -1e30f, l0 = 0.f, l1 = 0.f;

    for (int kt = 0; kt < 32; kt++) {
        const int s = kt & 1;
        if (kt + 1 < 32) { GF_ISS(kt + 1, s ^ 1); }
        asm volatile("cp.async.commit_group;");
        asm volatile("cp.async.wait_group 1;");
        __syncthreads();

        __nv_bfloat16* Ks = GF_K(s);
        __nv_bfloat16* Vs = GF_V(s);

        float sf[8][4];
#pragma unroll
        for (int nf = 0; nf < 8; nf++) {
#pragma unroll
            for (int i = 0; i < 4; i++) sf[nf][i] = 0.f;
#pragma unroll
            for (int ks = 0; ks < 4; ks++) {
                uint32_t kb[2];
                int row = nf * 8 + (lane & 7);
                int col = ks * 16 + ((lane >> 3) & 1) * 8;
                ldsm_x2(kb, cvta_s(&Ks[row * 72 + col]));
                mma_bf16(sf[nf], qf[ks], kb);
            }
        }

        float mx0 = -1e30f, mx1 = -1e30f;
#pragma unroll
        for (int nf = 0; nf < 8; nf++) {
            float a0 = maskS[kt * 64 + nf * 8 + 2 * tig];
            float a1 = maskS[kt * 64 + nf * 8 + 2 * tig + 1];
            sf[nf][0] = sf[nf][0] * 0.125f + a0;
            sf[nf][1] = sf[nf][1] * 0.125f + a1;
            sf[nf][2] = sf[nf][2] * 0.125f + a0;
            sf[nf][3] = sf[nf][3] * 0.125f + a1;
            mx0 = fmaxf(mx0, fmaxf(sf[nf][0], sf[nf][1]));
            mx1 = fmaxf(mx1, fmaxf(sf[nf][2], sf[nf][3]));
        }
        mx0 = fmaxf(mx0, __shfl_xor_sync(~0u, mx0, 1));
        mx0 = fmaxf(mx0, __shfl_xor_sync(~0u, mx0, 2));
        mx1 = fmaxf(mx1, __shfl_xor_sync(~0u, mx1, 1));
        mx1 = fmaxf(mx1, __shfl_xor_sync(~0u, mx1, 2));
        float mn0 = fmaxf(m0, mx0), mn1 = fmaxf(m1, mx1);
        float cr0 = __expf(m0 - mn0), cr1 = __expf(m1 - mn1);
        m0 = mn0; m1 = mn1;

        float ps0 = 0.f, ps1 = 0.f;
        uint32_t pa[4][4];
#pragma unroll
        for (int nf = 0; nf < 8; nf++) {
            float p0 = __expf(sf[nf][0] - mn0), p1 = __expf(sf[nf][1] - mn0);
            float p2 = __expf(sf[nf][2] - mn1), p3 = __expf(sf[nf][3] - mn1);
            ps0 += p0 + p1; ps1 += p2 + p3;
            int ks = nf >> 1;
            if (nf & 1) { pa[ks][2] = pack_bf16(p0, p1); pa[ks][3] = pack_bf16(p2, p3); }
            else        { pa[ks][0] = pack_bf16(p0, p1); pa[ks][1] = pack_bf16(p2, p3); }
        }
        ps0 += __shfl_xor_sync(~0u, ps0, 1); ps0 += __shfl_xor_sync(~0u, ps0, 2);
        ps1 += __shfl_xor_sync(~0u, ps1, 1); ps1 += __shfl_xor_sync(~0u, ps1, 2);
        l0 = l0 * cr0 + ps0; l1 = l1 * cr1 + ps1;
#pragma unroll
        for (int nf = 0; nf < 8; nf++) {
            of[nf][0] *= cr0; of[nf][1] *= cr0; of[nf][2] *= cr1; of[nf][3] *= cr1;
        }
#pragma unroll
        for (int nf = 0; nf < 8; nf++)
#pragma unroll
            for (int ks = 0; ks < 4; ks++) {
                uint32_t vb[2];
                ldsm_x2t(vb, cvta_s(&Vs[(ks * 16 + (lane & 15)) * 72 + nf * 8]));
                mma_bf16(of[nf], pa[ks], vb);
            }
        __syncthreads();
    }

    const float inv0 = 1.f / l0, inv1 = 1.f / l1;
    const int r0 = rowbase + qb * 128 + warp * 16 + g;
#pragma unroll
    for (int nf = 0; nf < 8; nf++) {
        int col = h * 64 + nf * 8 + 2 * tig;
        out[(size_t)r0 * HID + col]           = of[nf][0] * inv0;
        out[(size_t)r0 * HID + col + 1]       = of[nf][1] * inv0;
        out[(size_t)(r0 + 8) * HID + col]     = of[nf][2] * inv1;
        out[(size_t)(r0 + 8) * HID + col + 1] = of[nf][3] * inv1;
    }
}

// ---------------- local flash: bf16 3-term QK, 2-term PV, double-buffered ----------------
__global__ __launch_bounds__(256) void flash_local(float* __restrict__ out) {
    extern __shared__ char lsm[];
#define LF_KH(s) ((__nv_bfloat16*)(lsm + (s) * 36864))
#define LF_KL(s) ((__nv_bfloat16*)(lsm + (s) * 36864 + 9216))
#define LF_VH(s) ((__nv_bfloat16*)(lsm + (s) * 36864 + 18432))
#define LF_VL(s) ((__nv_bfloat16*)(lsm + (s) * 36864 + 27648))
    const int tid = threadIdx.x, lane = tid & 31, warp = tid >> 5;
    const int g = lane >> 2, tig = lane & 3;
    const int qb = blockIdx.x, by = blockIdx.y;
    const int b = by >> 3, h = by & 7;
    const int rowbase = b * SEQ;
    const int lr = tid >> 2, lch = tid & 3;

#define LF_ISS(kt, s) {                                                        \
        size_t go = (size_t)(rowbase + (kt) * 64 + lr) * 512 + h * 64 + lch * 16; \
        cp16(LF_KH(s) + lr * 72 + lch * 16,     &g_K2h[go]);                   \
        cp16(LF_KH(s) + lr * 72 + lch * 16 + 8, &g_K2h[go + 8]);               \
        cp16(LF_KL(s) + lr * 72 + lch * 16,     &g_K2l[go]);                   \
        cp16(LF_KL(s) + lr * 72 + lch * 16 + 8, &g_K2l[go + 8]);               \
        cp16(LF_VH(s) + lr * 72 + lch * 16,     &g_Vmh[go]);                   \
        cp16(LF_VH(s) + lr * 72 + lch * 16 + 8, &g_Vmh[go + 8]);               \
        cp16(LF_VL(s) + lr * 72 + lch * 16,     &g_Vml[go]);                   \
        cp16(LF_VL(s) + lr * 72 + lch * 16 + 8, &g_Vml[go + 8]); }

    // Q fragments (bf16 hi/lo) from fp32 gmem
    uint32_t qh[4][4], ql[4][4];
    const int qr0 = rowbase + qb * 128 + warp * 16 + g;
    const float* P0 = &g_Pf[(size_t)qr0 * LC + h * 64];
    const float* P1 = &g_Pf[(size_t)(qr0 + 8) * LC + h * 64];
#pragma unroll
    for (int ks = 0; ks < 4; ks++) {
        int c0 = ks * 16 + 2 * tig;
        pack_hl(P0[c0],     P0[c0 + 1], qh[ks][0], ql[ks][0]);
        pack_hl(P1[c0],     P1[c0 + 1], qh[ks][1], ql[ks][1]);
        pack_hl(P0[c0 + 8], P0[c0 + 9], qh[ks][2], ql[ks][2]);
        pack_hl(P1[c0 + 8], P1[c0 + 9], qh[ks][3], ql[ks][3]);
    }

    LF_ISS(0, 0); asm volatile("cp.async.commit_group;");

    float of[8][4];
#pragma unroll
    for (int nf = 0; nf < 8; nf++)
#pragma unroll
        for (int i = 0; i < 4; i++) of[nf][i] = 0.f;
    float m0 = -1e30f, m1 = -1e30f, l0 = 0.f, l1 = 0.f;

    for (int kt = 0; kt < 32; kt++) {
        const int s = kt & 1;
        if (kt + 1 < 32) { LF_ISS(kt + 1, s ^ 1); }
        asm volatile("cp.async.commit_group;");
        asm volatile("cp.async.wait_group 1;");
        __syncthreads();

        __nv_bfloat16* Kh = LF_KH(s);
        __nv_bfloat16* Kl = LF_KL(s);
        __nv_bfloat16* Vh = LF_VH(s);
        __nv_bfloat16* Vl = LF_VL(s);

        float sf[8][4];
#pragma unroll
        for (int nf = 0; nf < 8; nf++) {
#pragma unroll
            for (int i = 0; i < 4; i++) sf[nf][i] = 0.f;
#pragma unroll
            for (int ks = 0; ks < 4; ks++) {
                uint32_t kbh[2], kbl[2];
                int row = nf * 8 + (lane & 7);
                int col = ks * 16 + ((lane >> 3) & 1) * 8;
                ldsm_x2(kbh, cvta_s(&Kh[row * 72 + col]));
                ldsm_x2(kbl, cvta_s(&Kl[row * 72 + col]));
                mma_bf16(sf[nf], qh[ks], kbh);
                mma_bf16(sf[nf], ql[ks], kbh);
                mma_bf16(sf[nf], qh[ks], kbl);
            }
        }

        float mx0 = -1e30f, mx1 = -1e30f;
#pragma unroll
        for (int nf = 0; nf < 8; nf++) {
            sf[nf][0] *= 0.125f; sf[nf][1] *= 0.125f;
            sf[nf][2] *= 0.125f; sf[nf][3] *= 0.125f;
            mx0 = fmaxf(mx0, fmaxf(sf[nf][0], sf[nf][1]));
            mx1 = fmaxf(mx1, fmaxf(sf[nf][2], sf[nf][3]));
        }
        mx0 = fmaxf(mx0, __shfl_xor_sync(~0u, mx0, 1));
        mx0 = fmaxf(mx0, __shfl_xor_sync(~0u, mx0, 2));
        mx1 = fmaxf(mx1, __shfl_xor_sync(~0u, mx1, 1));
        mx1 = fmaxf(mx1, __shfl_xor_sync(~0u, mx1, 2));
        float mn0 = fmaxf(m0, mx0), mn1 = fmaxf(m1, mx1);
        float cr0 = __expf(m0 - mn0), cr1 = __expf(m1 - mn1);
        m0 = mn0; m1 = mn1;

        float ps0 = 0.f, ps1 = 0.f;
        uint32_t pah[4][4];
#pragma unroll
        for (int nf = 0; nf < 8; nf++) {
            float p0 = __expf(sf[nf][0] - mn0), p1 = __expf(sf[nf][1] - mn0);
            float p2 = __expf(sf[nf][2] - mn1), p3 = __expf(sf[nf][3] - mn1);
            ps0 += p0 + p1; ps1 += p2 + p3;
            int ks = nf >> 1;
            if (nf & 1) { pah[ks][2] = pack_bf16(p0, p1); pah[ks][3] = pack_bf16(p2, p3); }
            else        { pah[ks][0] = pack_bf16(p0, p1); pah[ks][1] = pack_bf16(p2, p3); }
        }
        ps0 += __shfl_xor_sync(~0u, ps0, 1); ps0 += __shfl_xor_sync(~0u, ps0, 2);
        ps1 += __shfl_xor_sync(~0u, ps1, 1); ps1 += __shfl_xor_sync(~0u, ps1, 2);
        l0 = l0 * cr0 + ps0; l1 = l1 * cr1 + ps1;
#pragma unroll
        for (int nf = 0; nf < 8; nf++) {
            of[nf][0] *= cr0; of[nf][1] *= cr0; of[nf][2] *= cr1; of[nf][3] *= cr1;
        }
#pragma unroll
        for (int nf = 0; nf < 8; nf++)
#pragma unroll
            for (int ks = 0; ks < 4; ks++) {
                uint32_t vbh[2], vbl[2];
                ldsm_x2t(vbh, cvta_s(&Vh[(ks * 16 + (lane & 15)) * 72 + nf * 8]));
                ldsm_x2t(vbl, cvta_s(&Vl[(ks * 16 + (lane & 15)) * 72 + nf * 8]));
                mma_bf16(of[nf], pah[ks], vbh);
                mma_bf16(of[nf], pah[ks], vbl);
            }
        __syncthreads();
    }

    const float inv0 = 1.f / l0, inv1 = 1.f / l1;
    const int r0 = rowbase + qb * 128 + warp * 16 + g;
#pragma unroll
    for (int nf = 0; nf < 8; nf++) {
        int col = (8 + h) * 64 + nf * 8 + 2 * tig;
        out[(size_t)r0 * HID + col]           = of[nf][0] * inv0;
        out[(size_t)r0 * HID + col + 1]       = of[nf][1] * inv0;
        out[(size_t)(r0 + 8) * HID + col]     = of[nf][2] * inv1;
        out[(size_t)(r0 + 8) * HID + col + 1] = of[nf][3] * inv1;
    }
}

// ---------------------------------------------------------------------------
extern "C" void kernel_launch(void* const* d_in, const int* in_sizes, int n_in,
                              void* d_out, int out_size) {
    (void)in_sizes; (void)n_in; (void)out_size;
    const float* X    = (const float*)d_in[0];
    const float* mask = (const float*)d_in[1];
    ProjArgs pa;
    for (int i = 0; i < 8; i++) {
        pa.w[i] = (const float*)d_in[2 + 2 * i];
        pa.b[i] = (const float*)d_in[3 + 2 * i];
    }
    float* out = (float*)d_out;

    const int PGSMEM = 61440 + 512;     // proj_g
    const int PLSMEM = 81920 + 512;     // proj_l
    const int GFSMEM = 26624 + 2 * 18432;   // flash_global = 63488
    const int LFSMEM = 2 * 36864;           // flash_local  = 73728
    cudaFuncSetAttribute(proj_g, cudaFuncAttributeMaxDynamicSharedMemorySize, PGSMEM);
    cudaFuncSetAttribute(proj_l, cudaFuncAttributeMaxDynamicSharedMemorySize, PLSMEM);
    cudaFuncSetAttribute(flash_global, cudaFuncAttributeMaxDynamicSharedMemorySize, GFSMEM);
    cudaFuncSetAttribute(flash_local, cudaFuncAttributeMaxDynamicSharedMemorySize, LFSMEM);

    split_X<<<4096, 256>>>(X);
    transW<<<dim3(16, 32, 8), 256>>>(pa);
    bias_cat<<<16, 256>>>(pa);
    proj_l<<<dim3(20, 32), 256, PLSMEM>>>();
    proj_g<<<dim3(12, 32), 256, PGSMEM>>>();
    compute_M_part<<<dim3(16, 8), 256>>>();
    reduce_M<<<256, 256>>>();
    lq_update<<<dim3(64, 8), 256>>>();
    prep_local<<<2048, 256>>>();
    flash_global<<<dim3(16, 16), 256, GFSMEM>>>(mask, out);
    flash_local<<<dim3(16, 16), 256, LFSMEM>>>(out);
}